// round 1
// baseline (speedup 1.0000x reference)
#include <cuda_runtime.h>

#define N_NODES 50000
#define N_EDGES 800000
#define E_TOT   (N_EDGES + N_NODES)   // 850000 with self-loops
#define NCOLS   256                   // heads * channels = 4*64
#define SLOPE   0.2f

// ---------------- scratch (device globals; no allocation allowed) ------------
__device__ float g_h[N_NODES * NCOLS];     // GEMM output / gather source
__device__ float g_x[N_NODES * NCOLS];     // layer activation ping buffer
__device__ float g_asrc[N_NODES * 4];
__device__ float g_adst[N_NODES * 4];
__device__ int   g_counts[N_NODES];
__device__ int   g_rowptr[N_NODES + 1];
__device__ int   g_cursor[N_NODES];
__device__ int   g_csr_src[E_TOT];

// ---------------- CSR build --------------------------------------------------
__global__ void zero_counts_k() {
    int i = blockIdx.x * blockDim.x + threadIdx.x;
    if (i < N_NODES) g_counts[i] = 0;
}

__global__ void hist_k(const int* __restrict__ ei) {
    int e = blockIdx.x * blockDim.x + threadIdx.x;
    if (e < E_TOT) {
        int d = (e < N_EDGES) ? ei[N_EDGES + e] : (e - N_EDGES);
        atomicAdd(&g_counts[d], 1);
    }
}

__global__ void scan_k() {
    __shared__ int sums[1024];
    int tid = threadIdx.x;
    const int chunk = (N_NODES + 1023) / 1024;   // 49
    int start = tid * chunk;
    int end   = min(start + chunk, N_NODES);
    int s = 0;
    for (int i = start; i < end; i++) s += g_counts[i];
    sums[tid] = s;
    __syncthreads();
    // Hillis-Steele inclusive scan
    for (int d = 1; d < 1024; d <<= 1) {
        int v = (tid >= d) ? sums[tid - d] : 0;
        __syncthreads();
        sums[tid] += v;
        __syncthreads();
    }
    int off = sums[tid] - s;  // exclusive prefix
    for (int i = start; i < end; i++) {
        g_rowptr[i] = off;
        g_cursor[i] = off;
        off += g_counts[i];
    }
    if (end == N_NODES) g_rowptr[N_NODES] = off;
}

__global__ void scatter_k(const int* __restrict__ ei) {
    int e = blockIdx.x * blockDim.x + threadIdx.x;
    if (e < E_TOT) {
        int s, d;
        if (e < N_EDGES) { s = ei[e]; d = ei[N_EDGES + e]; }
        else             { s = d = e - N_EDGES; }
        int pos = atomicAdd(&g_cursor[d], 1);
        g_csr_src[pos] = s;
    }
}

// ---------------- GEMM: C[M,256] = A[M,K] @ B[K,256] -------------------------
// 64x64 tile, BK=16, 256 threads, 4x4 register micro-tile per thread.
__global__ __launch_bounds__(256) void gemm_k(
    const float* __restrict__ A, const float* __restrict__ B,
    float* __restrict__ C, int M, int K)
{
    __shared__ float As[16][68];   // transposed A tile, padded for aligned float4
    __shared__ float Bs[16][64];

    int t  = threadIdx.x;
    int tx = t & 15;
    int ty = t >> 4;
    int row0 = blockIdx.y * 64;
    int col0 = blockIdx.x * 64;

    int ar = t >> 2;          // 0..63  A tile row
    int ak = (t & 3) * 4;     // 0,4,8,12
    int br = t >> 4;          // 0..15  B tile row
    int bc = (t & 15) * 4;

    float acc[4][4] = {};

    for (int k0 = 0; k0 < K; k0 += 16) {
        float4 av = make_float4(0.f, 0.f, 0.f, 0.f);
        if (row0 + ar < M)
            av = *(const float4*)(A + (size_t)(row0 + ar) * K + k0 + ak);
        As[ak + 0][ar] = av.x;
        As[ak + 1][ar] = av.y;
        As[ak + 2][ar] = av.z;
        As[ak + 3][ar] = av.w;

        float4 bv = *(const float4*)(B + (size_t)(k0 + br) * NCOLS + col0 + bc);
        *(float4*)&Bs[br][bc] = bv;
        __syncthreads();

#pragma unroll
        for (int kk = 0; kk < 16; kk++) {
            float4 ra = *(const float4*)&As[kk][ty * 4];
            float4 rb = *(const float4*)&Bs[kk][tx * 4];
            float a0 = ra.x, a1 = ra.y, a2 = ra.z, a3 = ra.w;
            float b0 = rb.x, b1 = rb.y, b2 = rb.z, b3 = rb.w;
            acc[0][0] += a0 * b0; acc[0][1] += a0 * b1; acc[0][2] += a0 * b2; acc[0][3] += a0 * b3;
            acc[1][0] += a1 * b0; acc[1][1] += a1 * b1; acc[1][2] += a1 * b2; acc[1][3] += a1 * b3;
            acc[2][0] += a2 * b0; acc[2][1] += a2 * b1; acc[2][2] += a2 * b2; acc[2][3] += a2 * b3;
            acc[3][0] += a3 * b0; acc[3][1] += a3 * b1; acc[3][2] += a3 * b2; acc[3][3] += a3 * b3;
        }
        __syncthreads();
    }

#pragma unroll
    for (int i = 0; i < 4; i++) {
        int r = row0 + ty * 4 + i;
        if (r < M)
            *(float4*)(C + (size_t)r * NCOLS + col0 + tx * 4) =
                make_float4(acc[i][0], acc[i][1], acc[i][2], acc[i][3]);
    }
}

// ---------------- per-node attention logits ----------------------------------
// one warp per node; 4 heads, 64 channels each.
__global__ __launch_bounds__(256) void alpha_k(
    const float* __restrict__ h,
    const float* __restrict__ a_src, const float* __restrict__ a_dst)
{
    int gw   = (blockIdx.x * blockDim.x + threadIdx.x) >> 5;
    int lane = threadIdx.x & 31;
    if (gw >= N_NODES) return;
    const float* hr = h + (size_t)gw * NCOLS;
#pragma unroll
    for (int head = 0; head < 4; head++) {
        int c = head * 64 + lane;
        float v0 = hr[c], v1 = hr[c + 32];
        float s = v0 * a_src[c] + v1 * a_src[c + 32];
        float d = v0 * a_dst[c] + v1 * a_dst[c + 32];
#pragma unroll
        for (int o = 16; o; o >>= 1) {
            s += __shfl_xor_sync(0xffffffffu, s, o);
            d += __shfl_xor_sync(0xffffffffu, d, o);
        }
        if (lane == 0) {
            g_asrc[gw * 4 + head] = s;
            g_adst[gw * 4 + head] = d;
        }
    }
}

// ---------------- aggregation: online segment-softmax + gather ---------------
// one warp per (dst, head); 2 channels per lane.
__global__ __launch_bounds__(256) void aggr_k(
    const float* __restrict__ h, const float* __restrict__ bias,
    float* __restrict__ out)
{
    int gw   = (blockIdx.x * blockDim.x + threadIdx.x) >> 5;
    int lane = threadIdx.x & 31;
    if (gw >= N_NODES * 4) return;
    int d    = gw >> 2;
    int head = gw & 3;

    int beg = g_rowptr[d];
    int end = g_rowptr[d + 1];
    float adst = g_adst[d * 4 + head];

    float m = -1e30f, ssum = 0.f, a0 = 0.f, a1 = 0.f;
    for (int i = beg; i < end; i++) {
        int s = g_csr_src[i];
        float e = g_asrc[s * 4 + head] + adst;
        e = e > 0.f ? e : SLOPE * e;
        float w;
        if (e > m) {
            float f = __expf(m - e);
            ssum *= f; a0 *= f; a1 *= f;
            m = e; w = 1.f;
        } else {
            w = __expf(e - m);
        }
        ssum += w;
        const float* hp = h + (size_t)s * NCOLS + head * 64;
        a0 += w * hp[lane];
        a1 += w * hp[lane + 32];
    }
    float inv = 1.f / ssum;
    int c0 = head * 64 + lane;
    float o0 = a0 * inv + bias[c0];
    float o1 = a1 * inv + bias[c0 + 32];
    // ELU
    o0 = o0 > 0.f ? o0 : (expf(o0) - 1.f);
    o1 = o1 > 0.f ? o1 : (expf(o1) - 1.f);
    out[(size_t)d * NCOLS + c0]      = o0;
    out[(size_t)d * NCOLS + c0 + 32] = o1;
}

// ---------------- driver ------------------------------------------------------
static void run_layer(const float* x, int K, const float* W,
                      const float* asv, const float* adv, const float* bias,
                      float* hbuf, float* out)
{
    dim3 gg(NCOLS / 64, (N_NODES + 63) / 64);
    gemm_k<<<gg, 256>>>(x, W, hbuf, N_NODES, K);
    alpha_k<<<(N_NODES * 32 + 255) / 256, 256>>>(hbuf, asv, adv);
    aggr_k<<<(N_NODES * 4 * 32 + 255) / 256, 256>>>(hbuf, bias, out);
}

extern "C" void kernel_launch(void* const* d_in, const int* in_sizes, int n_in,
                              void* d_out, int out_size)
{
    const float* inp = (const float*)d_in[0];
    const int*   ei  = (const int*)d_in[1];
    const float* W1  = (const float*)d_in[2];
    const float* as1 = (const float*)d_in[3];
    const float* ad1 = (const float*)d_in[4];
    const float* b1  = (const float*)d_in[5];
    const float* W2  = (const float*)d_in[6];
    const float* as2 = (const float*)d_in[7];
    const float* ad2 = (const float*)d_in[8];
    const float* b2  = (const float*)d_in[9];
    const float* W3  = (const float*)d_in[10];
    const float* as3 = (const float*)d_in[11];
    const float* ad3 = (const float*)d_in[12];
    const float* b3  = (const float*)d_in[13];
    float* out = (float*)d_out;

    float *hbuf, *xbuf;
    cudaGetSymbolAddress((void**)&hbuf, g_h);
    cudaGetSymbolAddress((void**)&xbuf, g_x);

    // CSR build (constant across the 3 layers)
    zero_counts_k<<<(N_NODES + 255) / 256, 256>>>();
    hist_k<<<(E_TOT + 255) / 256, 256>>>(ei);
    scan_k<<<1, 1024>>>();
    scatter_k<<<(E_TOT + 255) / 256, 256>>>(ei);

    run_layer(inp,  128, W1, as1, ad1, b1, hbuf, xbuf);
    run_layer(xbuf, 256, W2, as2, ad2, b2, hbuf, xbuf);
    run_layer(xbuf, 256, W3, as3, ad3, b3, hbuf, out);
}

// round 3
// speedup vs baseline: 1.4533x; 1.4533x over previous
#include <cuda_runtime.h>
#include <cstdint>

#define N_NODES 50000
#define N_EDGES 800000
#define E_TOT   (N_EDGES + N_NODES)
#define NCOLS   256
#define SLOPE   0.2f

// ---------------- scratch (device globals) -----------------------------------
__device__ float g_h[N_NODES * NCOLS];
__device__ float g_x[N_NODES * NCOLS];
__device__ float g_bt1[256 * 128];     // W1^T, tf32-rounded, [n][k]
__device__ float g_bt2[256 * 256];
__device__ float g_bt3[256 * 256];
__device__ float g_asrc[N_NODES * 4];
__device__ float g_adst[N_NODES * 4];
__device__ int   g_counts[N_NODES];
__device__ int   g_rowptr[N_NODES + 1];
__device__ int   g_cursor[N_NODES];
__device__ int   g_csr_src[E_TOT];

__device__ __forceinline__ float tf32r(float x) {
    float y;
    asm("cvt.rna.tf32.f32 %0, %1;" : "=f"(y) : "f"(x));
    return y;
}

// ---------------- CSR build ----------------------------------------------------
__global__ void zero_counts_k() {
    int i = blockIdx.x * blockDim.x + threadIdx.x;
    if (i < N_NODES) g_counts[i] = 0;
}
__global__ void hist_k(const int* __restrict__ ei) {
    int e = blockIdx.x * blockDim.x + threadIdx.x;
    if (e < E_TOT) {
        int d = (e < N_EDGES) ? ei[N_EDGES + e] : (e - N_EDGES);
        atomicAdd(&g_counts[d], 1);
    }
}
__global__ void scan_k() {
    __shared__ int sums[1024];
    int tid = threadIdx.x;
    const int chunk = (N_NODES + 1023) / 1024;
    int start = tid * chunk;
    int end = min(start + chunk, N_NODES);
    int s = 0;
    for (int i = start; i < end; i++) s += g_counts[i];
    sums[tid] = s;
    __syncthreads();
    for (int d = 1; d < 1024; d <<= 1) {
        int v = (tid >= d) ? sums[tid - d] : 0;
        __syncthreads();
        sums[tid] += v;
        __syncthreads();
    }
    int off = sums[tid] - s;
    for (int i = start; i < end; i++) {
        g_rowptr[i] = off;
        g_cursor[i] = off;
        off += g_counts[i];
    }
    if (end == N_NODES) g_rowptr[N_NODES] = off;
}
__global__ void scatter_k(const int* __restrict__ ei) {
    int e = blockIdx.x * blockDim.x + threadIdx.x;
    if (e < E_TOT) {
        int s, d;
        if (e < N_EDGES) { s = ei[e]; d = ei[N_EDGES + e]; }
        else             { s = d = e - N_EDGES; }
        int pos = atomicAdd(&g_cursor[d], 1);
        g_csr_src[pos] = s;
    }
}

// ---------------- transpose + tf32-round weights -------------------------------
__global__ void transpose_rnd_k(const float* __restrict__ W, float* __restrict__ Bt, int K) {
    int idx = blockIdx.x * blockDim.x + threadIdx.x;
    if (idx >= 256 * K) return;
    int n = idx / K, k = idx - n * K;
    Bt[idx] = tf32r(W[k * 256 + n]);   // Bt[n][k] = W[k][n]
}

// ---------------- mma.sync tf32 GEMM + fused attention logits -------------------
// C[row0:+128][col0:+128] = A @ Bt^T, plus g_asrc/g_adst (warp tile = 1 head).
// Fragment layouts per PTX m16n8k8 tf32:
//   A: a0(m=g,k=tg) a1(m=g+8,k=tg) a2(m=g,k=tg+4) a3(m=g+8,k=tg+4)
//   B: b0(n=g,k=tg) b1(n=g,k=tg+4)
//   C: c0(m=g,n=2tg) c1(m=g,n=2tg+1) c2(m=g+8,n=2tg) c3(m=g+8,n=2tg+1)
#define SMS 36   // smem row stride in floats -> bank = (4m+k)&31, conflict-free

__global__ __launch_bounds__(256, 2) void gemm_mma(
    const float* __restrict__ A, const float* __restrict__ Bt,
    float* __restrict__ C,
    const float* __restrict__ avs, const float* __restrict__ avd,
    int M, int K)
{
    __shared__ float As[128 * SMS];
    __shared__ float Bs[128 * SMS];

    int t = threadIdx.x;
    int lane = t & 31;
    int wid  = t >> 5;
    int wm = wid & 3;        // 32-row warp tile
    int wn = wid >> 2;       // 64-col warp tile (= one head)
    int g  = lane >> 2;
    int tg = lane & 3;
    int row0 = blockIdx.y * 128;
    int col0 = blockIdx.x * 128;

    const int lr = t >> 3;         // 0..31
    const int c4 = (t & 7) * 4;    // 0..28

    float c[2][8][4] = {};

    for (int k0 = 0; k0 < K; k0 += 32) {
#pragma unroll
        for (int i = 0; i < 4; i++) {
            int r = lr + 32 * i;
            float4 v = make_float4(0.f, 0.f, 0.f, 0.f);
            if (row0 + r < M)
                v = *(const float4*)(A + (size_t)(row0 + r) * K + k0 + c4);
            v.x = tf32r(v.x); v.y = tf32r(v.y); v.z = tf32r(v.z); v.w = tf32r(v.w);
            *(float4*)(As + r * SMS + c4) = v;
            float4 w = *(const float4*)(Bt + (size_t)(col0 + r) * K + k0 + c4);
            *(float4*)(Bs + r * SMS + c4) = w;
        }
        __syncthreads();

#pragma unroll
        for (int ks = 0; ks < 4; ks++) {
            int kb = ks * 8;
            uint32_t a[2][4], b[8][2];
#pragma unroll
            for (int mf = 0; mf < 2; mf++) {
                int r = wm * 32 + mf * 16 + g;
                a[mf][0] = __float_as_uint(As[r * SMS + kb + tg]);
                a[mf][1] = __float_as_uint(As[(r + 8) * SMS + kb + tg]);
                a[mf][2] = __float_as_uint(As[r * SMS + kb + tg + 4]);
                a[mf][3] = __float_as_uint(As[(r + 8) * SMS + kb + tg + 4]);
            }
#pragma unroll
            for (int nf = 0; nf < 8; nf++) {
                int n = wn * 64 + nf * 8 + g;
                b[nf][0] = __float_as_uint(Bs[n * SMS + kb + tg]);
                b[nf][1] = __float_as_uint(Bs[n * SMS + kb + tg + 4]);
            }
#pragma unroll
            for (int mf = 0; mf < 2; mf++)
#pragma unroll
                for (int nf = 0; nf < 8; nf++)
                    asm volatile(
                        "mma.sync.aligned.m16n8k8.row.col.f32.tf32.tf32.f32 "
                        "{%0,%1,%2,%3}, {%4,%5,%6,%7}, {%8,%9}, {%0,%1,%2,%3};"
                        : "+f"(c[mf][nf][0]), "+f"(c[mf][nf][1]),
                          "+f"(c[mf][nf][2]), "+f"(c[mf][nf][3])
                        : "r"(a[mf][0]), "r"(a[mf][1]), "r"(a[mf][2]), "r"(a[mf][3]),
                          "r"(b[nf][0]), "r"(b[nf][1]));
        }
        __syncthreads();
    }

    // epilogue: store C + fused per-head attention dots
    int head = (col0 >> 6) + wn;
#pragma unroll
    for (int mf = 0; mf < 2; mf++) {
        int r0 = row0 + wm * 32 + mf * 16 + g;
        int r1 = r0 + 8;
        float sv0 = 0.f, sv1 = 0.f, dv0 = 0.f, dv1 = 0.f;
#pragma unroll
        for (int nf = 0; nf < 8; nf++) {
            int col = col0 + wn * 64 + nf * 8 + tg * 2;
            float x0 = c[mf][nf][0], x1 = c[mf][nf][1];
            float x2 = c[mf][nf][2], x3 = c[mf][nf][3];
            if (r0 < M) *(float2*)(C + (size_t)r0 * NCOLS + col) = make_float2(x0, x1);
            if (r1 < M) *(float2*)(C + (size_t)r1 * NCOLS + col) = make_float2(x2, x3);
            float w0 = __ldg(avs + col), w1 = __ldg(avs + col + 1);
            float u0 = __ldg(avd + col), u1 = __ldg(avd + col + 1);
            sv0 += x0 * w0 + x1 * w1;
            sv1 += x2 * w0 + x3 * w1;
            dv0 += x0 * u0 + x1 * u1;
            dv1 += x2 * u0 + x3 * u1;
        }
        sv0 += __shfl_xor_sync(0xffffffffu, sv0, 1);
        sv0 += __shfl_xor_sync(0xffffffffu, sv0, 2);
        sv1 += __shfl_xor_sync(0xffffffffu, sv1, 1);
        sv1 += __shfl_xor_sync(0xffffffffu, sv1, 2);
        dv0 += __shfl_xor_sync(0xffffffffu, dv0, 1);
        dv0 += __shfl_xor_sync(0xffffffffu, dv0, 2);
        dv1 += __shfl_xor_sync(0xffffffffu, dv1, 1);
        dv1 += __shfl_xor_sync(0xffffffffu, dv1, 2);
        if (tg == 0) {
            if (r0 < M) { g_asrc[r0 * 4 + head] = sv0; g_adst[r0 * 4 + head] = dv0; }
            if (r1 < M) { g_asrc[r1 * 4 + head] = sv1; g_adst[r1 * 4 + head] = dv1; }
        }
    }
}

// ---------------- aggregation: online segment-softmax + gather -----------------
__global__ __launch_bounds__(256) void aggr_k(
    const float* __restrict__ h, const float* __restrict__ bias,
    float* __restrict__ out)
{
    int gw   = (blockIdx.x * blockDim.x + threadIdx.x) >> 5;
    int lane = threadIdx.x & 31;
    if (gw >= N_NODES * 4) return;
    int d = gw >> 2;
    int head = gw & 3;

    int beg = g_rowptr[d];
    int end = g_rowptr[d + 1];
    float adst = g_adst[d * 4 + head];

    float m = -1e30f, ssum = 0.f, a0 = 0.f, a1 = 0.f;
    for (int i = beg; i < end; i++) {
        int s = g_csr_src[i];
        float e = g_asrc[s * 4 + head] + adst;
        e = e > 0.f ? e : SLOPE * e;
        float w;
        if (e > m) {
            float f = __expf(m - e);
            ssum *= f; a0 *= f; a1 *= f;
            m = e; w = 1.f;
        } else {
            w = __expf(e - m);
        }
        ssum += w;
        const float* hp = h + (size_t)s * NCOLS + head * 64;
        a0 += w * hp[lane];
        a1 += w * hp[lane + 32];
    }
    float inv = 1.f / ssum;
    int c0 = head * 64 + lane;
    float o0 = a0 * inv + bias[c0];
    float o1 = a1 * inv + bias[c0 + 32];
    o0 = o0 > 0.f ? o0 : (expf(o0) - 1.f);
    o1 = o1 > 0.f ? o1 : (expf(o1) - 1.f);
    out[(size_t)d * NCOLS + c0]      = o0;
    out[(size_t)d * NCOLS + c0 + 32] = o1;
}

// ---------------- driver ---------------------------------------------------------
static void run_layer(const float* x, int K, const float* bt,
                      const float* asv, const float* adv, const float* bias,
                      float* hbuf, float* out)
{
    dim3 grid(2, (N_NODES + 127) / 128);
    gemm_mma<<<grid, 256>>>(x, bt, hbuf, asv, adv, N_NODES, K);
    aggr_k<<<(N_NODES * 4 * 32 + 255) / 256, 256>>>(hbuf, bias, out);
}

extern "C" void kernel_launch(void* const* d_in, const int* in_sizes, int n_in,
                              void* d_out, int out_size)
{
    const float* inp = (const float*)d_in[0];
    const int*   ei  = (const int*)d_in[1];
    const float* W1  = (const float*)d_in[2];
    const float* as1 = (const float*)d_in[3];
    const float* ad1 = (const float*)d_in[4];
    const float* b1  = (const float*)d_in[5];
    const float* W2  = (const float*)d_in[6];
    const float* as2 = (const float*)d_in[7];
    const float* ad2 = (const float*)d_in[8];
    const float* b2  = (const float*)d_in[9];
    const float* W3  = (const float*)d_in[10];
    const float* as3 = (const float*)d_in[11];
    const float* ad3 = (const float*)d_in[12];
    const float* b3  = (const float*)d_in[13];
    float* out = (float*)d_out;

    float *hbuf, *xbuf, *bt1, *bt2, *bt3;
    cudaGetSymbolAddress((void**)&hbuf, g_h);
    cudaGetSymbolAddress((void**)&xbuf, g_x);
    cudaGetSymbolAddress((void**)&bt1, g_bt1);
    cudaGetSymbolAddress((void**)&bt2, g_bt2);
    cudaGetSymbolAddress((void**)&bt3, g_bt3);

    // CSR build (constant across layers)
    zero_counts_k<<<(N_NODES + 255) / 256, 256>>>();
    hist_k<<<(E_TOT + 255) / 256, 256>>>(ei);
    scan_k<<<1, 1024>>>();
    scatter_k<<<(E_TOT + 255) / 256, 256>>>(ei);

    // weight transposes (tf32-rounded)
    transpose_rnd_k<<<(256 * 128 + 255) / 256, 256>>>(W1, bt1, 128);
    transpose_rnd_k<<<(256 * 256 + 255) / 256, 256>>>(W2, bt2, 256);
    transpose_rnd_k<<<(256 * 256 + 255) / 256, 256>>>(W3, bt3, 256);

    run_layer(inp,  128, bt1, as1, ad1, b1, hbuf, xbuf);
    run_layer(xbuf, 256, bt2, as2, ad2, b2, hbuf, xbuf);
    run_layer(xbuf, 256, bt3, as3, ad3, b3, hbuf, out);
}

// round 4
// speedup vs baseline: 1.6432x; 1.1307x over previous
#include <cuda_runtime.h>
#include <cstdint>

#define N_NODES 50000
#define N_EDGES 800000
#define E_TOT   (N_EDGES + N_NODES)
#define NCOLS   256
#define SLOPE   0.2f

// ---------------- scratch (device globals) -----------------------------------
__device__ float g_h[N_NODES * NCOLS];
__device__ float g_x[N_NODES * NCOLS];
__device__ float g_bt1[256 * 128];     // W^T, tf32-rounded, [n][k]
__device__ float g_bt2[256 * 256];
__device__ float g_bt3[256 * 256];
__device__ float g_asrc[N_NODES * 4];
__device__ float g_adst[N_NODES * 4];
__device__ int   g_counts[N_NODES];
__device__ int   g_rowptr[N_NODES + 1];
__device__ int   g_cursor[N_NODES];
__device__ int   g_csr_src[E_TOT];

__device__ __forceinline__ float tf32r(float x) {
    float y;
    asm("cvt.rna.tf32.f32 %0, %1;" : "=f"(y) : "f"(x));
    return y;
}
__device__ __forceinline__ void cpa16(uint32_t sdst, const void* gsrc, int srcsize) {
    asm volatile("cp.async.cg.shared.global [%0], [%1], 16, %2;"
                 :: "r"(sdst), "l"(gsrc), "r"(srcsize));
}

// ---------------- CSR build ----------------------------------------------------
__global__ void zero_counts_k() {
    int i = blockIdx.x * blockDim.x + threadIdx.x;
    if (i < N_NODES) g_counts[i] = 0;
}
__global__ void hist_k(const int* __restrict__ ei) {
    int e = blockIdx.x * blockDim.x + threadIdx.x;
    if (e < E_TOT) {
        int d = (e < N_EDGES) ? ei[N_EDGES + e] : (e - N_EDGES);
        atomicAdd(&g_counts[d], 1);
    }
}
__global__ void scan_k() {
    __shared__ int sums[1024];
    int tid = threadIdx.x;
    const int chunk = (N_NODES + 1023) / 1024;
    int start = tid * chunk;
    int end = min(start + chunk, N_NODES);
    int s = 0;
    for (int i = start; i < end; i++) s += g_counts[i];
    sums[tid] = s;
    __syncthreads();
    for (int d = 1; d < 1024; d <<= 1) {
        int v = (tid >= d) ? sums[tid - d] : 0;
        __syncthreads();
        sums[tid] += v;
        __syncthreads();
    }
    int off = sums[tid] - s;
    for (int i = start; i < end; i++) {
        g_rowptr[i] = off;
        g_cursor[i] = off;
        off += g_counts[i];
    }
    if (end == N_NODES) g_rowptr[N_NODES] = off;
}
__global__ void scatter_k(const int* __restrict__ ei) {
    int e = blockIdx.x * blockDim.x + threadIdx.x;
    if (e < E_TOT) {
        int s, d;
        if (e < N_EDGES) { s = ei[e]; d = ei[N_EDGES + e]; }
        else             { s = d = e - N_EDGES; }
        int pos = atomicAdd(&g_cursor[d], 1);
        g_csr_src[pos] = s;
    }
}

// ---------------- prep kernels ---------------------------------------------------
__global__ void transpose_rnd_k(const float* __restrict__ W, float* __restrict__ Bt, int K) {
    int idx = blockIdx.x * blockDim.x + threadIdx.x;
    if (idx >= 256 * K) return;
    int n = idx / K, k = idx - n * K;
    Bt[idx] = tf32r(W[k * 256 + n]);
}
__global__ void round_k(const float* __restrict__ in, float* __restrict__ o, int n) {
    int i = blockIdx.x * blockDim.x + threadIdx.x;
    if (i < n) o[i] = tf32r(in[i]);
}

// ---------------- cp.async double-buffered tf32 GEMM + fused alpha --------------
// 4 warps, CTA tile 128x128, warp tile 64x64 (one head per warp column band).
#define SMS 36
#define TILE_F (128 * SMS)

__global__ __launch_bounds__(128, 2) void gemm_mma(
    const float* __restrict__ A, const float* __restrict__ Bt,
    float* __restrict__ C,
    const float* __restrict__ avs, const float* __restrict__ avd,
    int M, int K)
{
    extern __shared__ float sm[];
    float* Abuf = sm;                // [2][TILE_F]
    float* Bbuf = sm + 2 * TILE_F;   // [2][TILE_F]
    uint32_t sA0 = (uint32_t)__cvta_generic_to_shared(Abuf);
    uint32_t sB0 = (uint32_t)__cvta_generic_to_shared(Bbuf);

    int t = threadIdx.x;
    int lane = t & 31, wid = t >> 5;
    int wm = wid & 1, wn = wid >> 1;
    int g = lane >> 2, tg = lane & 3;
    int row0 = blockIdx.y * 128;
    int col0 = blockIdx.x * 128;

    const int nch = K >> 5;

    // --- async issue of chunk kc into buffer buf ---
    auto issue = [&](int kc, int buf) {
        int k0 = kc << 5;
        uint32_t sa = sA0 + buf * (TILE_F * 4);
        uint32_t sb = sB0 + buf * (TILE_F * 4);
#pragma unroll
        for (int i = 0; i < 8; i++) {
            int idx = t + (i << 7);
            int r = idx >> 3, c16 = (idx & 7) << 2;
            int gr = row0 + r;
            const float* srcA = A + (size_t)min(gr, M - 1) * K + k0 + c16;
            cpa16(sa + (r * SMS + c16) * 4, srcA, gr < M ? 16 : 0);
            const float* srcB = Bt + (size_t)(col0 + r) * K + k0 + c16;
            cpa16(sb + (r * SMS + c16) * 4, srcB, 16);
        }
        asm volatile("cp.async.commit_group;" ::: "memory");
    };

    float c[4][8][4] = {};
    issue(0, 0);

    for (int kc = 0; kc < nch; kc++) {
        int buf = kc & 1;
        if (kc + 1 < nch) {
            issue(kc + 1, buf ^ 1);
            asm volatile("cp.async.wait_group 1;" ::: "memory");
        } else {
            asm volatile("cp.async.wait_group 0;" ::: "memory");
        }
        __syncthreads();
        const float* Ab = Abuf + buf * TILE_F;
        const float* Bb = Bbuf + buf * TILE_F;
#pragma unroll
        for (int ks = 0; ks < 4; ks++) {
            int kb = ks * 8;
            uint32_t a[4][4], b[8][2];
#pragma unroll
            for (int mf = 0; mf < 4; mf++) {
                int r = wm * 64 + mf * 16 + g;
                a[mf][0] = __float_as_uint(Ab[r * SMS + kb + tg]);
                a[mf][1] = __float_as_uint(Ab[(r + 8) * SMS + kb + tg]);
                a[mf][2] = __float_as_uint(Ab[r * SMS + kb + tg + 4]);
                a[mf][3] = __float_as_uint(Ab[(r + 8) * SMS + kb + tg + 4]);
            }
#pragma unroll
            for (int nf = 0; nf < 8; nf++) {
                int n = wn * 64 + nf * 8 + g;
                b[nf][0] = __float_as_uint(Bb[n * SMS + kb + tg]);
                b[nf][1] = __float_as_uint(Bb[n * SMS + kb + tg + 4]);
            }
#pragma unroll
            for (int mf = 0; mf < 4; mf++)
#pragma unroll
                for (int nf = 0; nf < 8; nf++)
                    asm volatile(
                        "mma.sync.aligned.m16n8k8.row.col.f32.tf32.tf32.f32 "
                        "{%0,%1,%2,%3}, {%4,%5,%6,%7}, {%8,%9}, {%0,%1,%2,%3};"
                        : "+f"(c[mf][nf][0]), "+f"(c[mf][nf][1]),
                          "+f"(c[mf][nf][2]), "+f"(c[mf][nf][3])
                        : "r"(a[mf][0]), "r"(a[mf][1]), "r"(a[mf][2]), "r"(a[mf][3]),
                          "r"(b[nf][0]), "r"(b[nf][1]));
        }
        __syncthreads();
    }

    // epilogue: store C + fused per-head attention dots (warp cols = one head)
    int head = (col0 >> 6) + wn;
#pragma unroll
    for (int mf = 0; mf < 4; mf++) {
        int r0 = row0 + wm * 64 + mf * 16 + g;
        int r1 = r0 + 8;
        float sv0 = 0.f, sv1 = 0.f, dv0 = 0.f, dv1 = 0.f;
#pragma unroll
        for (int nf = 0; nf < 8; nf++) {
            int col = col0 + wn * 64 + nf * 8 + tg * 2;
            float x0 = c[mf][nf][0], x1 = c[mf][nf][1];
            float x2 = c[mf][nf][2], x3 = c[mf][nf][3];
            if (r0 < M) *(float2*)(C + (size_t)r0 * NCOLS + col) = make_float2(x0, x1);
            if (r1 < M) *(float2*)(C + (size_t)r1 * NCOLS + col) = make_float2(x2, x3);
            float w0 = __ldg(avs + col), w1 = __ldg(avs + col + 1);
            float u0 = __ldg(avd + col), u1 = __ldg(avd + col + 1);
            sv0 += x0 * w0 + x1 * w1;
            sv1 += x2 * w0 + x3 * w1;
            dv0 += x0 * u0 + x1 * u1;
            dv1 += x2 * u0 + x3 * u1;
        }
        sv0 += __shfl_xor_sync(0xffffffffu, sv0, 1);
        sv0 += __shfl_xor_sync(0xffffffffu, sv0, 2);
        sv1 += __shfl_xor_sync(0xffffffffu, sv1, 1);
        sv1 += __shfl_xor_sync(0xffffffffu, sv1, 2);
        dv0 += __shfl_xor_sync(0xffffffffu, dv0, 1);
        dv0 += __shfl_xor_sync(0xffffffffu, dv0, 2);
        dv1 += __shfl_xor_sync(0xffffffffu, dv1, 1);
        dv1 += __shfl_xor_sync(0xffffffffu, dv1, 2);
        if (tg == 0) {
            if (r0 < M) { g_asrc[r0 * 4 + head] = sv0; g_adst[r0 * 4 + head] = dv0; }
            if (r1 < M) { g_asrc[r1 * 4 + head] = sv1; g_adst[r1 * 4 + head] = dv1; }
        }
    }
}

// ---------------- aggregation: chunked warp softmax + pipelined gather ----------
__global__ __launch_bounds__(256) void aggr_k(
    const float* __restrict__ h, const float* __restrict__ bias,
    float* __restrict__ out, int do_round)
{
    int gw   = (blockIdx.x * blockDim.x + threadIdx.x) >> 5;
    int lane = threadIdx.x & 31;
    if (gw >= N_NODES * 4) return;
    int d = gw >> 2;
    int head = gw & 3;

    int beg = g_rowptr[d];
    int end = g_rowptr[d + 1];
    float adst = g_adst[d * 4 + head];

    float m = -1e30f, ssum = 0.f, a0 = 0.f, a1 = 0.f;

    for (int base = beg; base < end; base += 32) {
        int i = base + lane;
        bool v = i < end;
        int s_l = v ? g_csr_src[i] : 0;
        float e_l = -1e30f;
        if (v) {
            float e = g_asrc[s_l * 4 + head] + adst;
            e_l = e > 0.f ? e : SLOPE * e;
        }
        // chunk max
        float cm = e_l;
#pragma unroll
        for (int o = 16; o; o >>= 1)
            cm = fmaxf(cm, __shfl_xor_sync(0xffffffffu, cm, o));
        float mnew = fmaxf(m, cm);
        float sc = __expf(m - mnew);
        ssum *= sc; a0 *= sc; a1 *= sc; m = mnew;
        float w_l = v ? __expf(e_l - m) : 0.f;
        float ws = w_l;
#pragma unroll
        for (int o = 16; o; o >>= 1)
            ws += __shfl_xor_sync(0xffffffffu, ws, o);
        ssum += ws;

        int n = min(32, end - base);
        int j = 0;
        for (; j + 2 <= n; j += 2) {
            int   s0 = __shfl_sync(0xffffffffu, s_l, j);
            int   s1 = __shfl_sync(0xffffffffu, s_l, j + 1);
            float w0 = __shfl_sync(0xffffffffu, w_l, j);
            float w1 = __shfl_sync(0xffffffffu, w_l, j + 1);
            const float* h0 = h + (size_t)s0 * NCOLS + head * 64;
            const float* h1 = h + (size_t)s1 * NCOLS + head * 64;
            float p0 = h0[lane], p1 = h0[lane + 32];
            float q0 = h1[lane], q1 = h1[lane + 32];
            a0 += w0 * p0 + w1 * q0;
            a1 += w0 * p1 + w1 * q1;
        }
        if (j < n) {
            int   s0 = __shfl_sync(0xffffffffu, s_l, j);
            float w0 = __shfl_sync(0xffffffffu, w_l, j);
            const float* h0 = h + (size_t)s0 * NCOLS + head * 64;
            a0 += w0 * h0[lane];
            a1 += w0 * h0[lane + 32];
        }
    }

    float inv = 1.f / ssum;
    int c0 = head * 64 + lane;
    float o0 = a0 * inv + bias[c0];
    float o1 = a1 * inv + bias[c0 + 32];
    o0 = o0 > 0.f ? o0 : (__expf(o0) - 1.f);
    o1 = o1 > 0.f ? o1 : (__expf(o1) - 1.f);
    if (do_round) { o0 = tf32r(o0); o1 = tf32r(o1); }
    out[(size_t)d * NCOLS + c0]      = o0;
    out[(size_t)d * NCOLS + c0 + 32] = o1;
}

// ---------------- driver ---------------------------------------------------------
#define GEMM_SMEM (4 * TILE_F * 4)   // 73728 bytes

static void run_layer(const float* x, int K, const float* bt,
                      const float* asv, const float* adv, const float* bias,
                      float* hbuf, float* out, int do_round)
{
    dim3 grid(2, (N_NODES + 127) / 128);
    gemm_mma<<<grid, 128, GEMM_SMEM>>>(x, bt, hbuf, asv, adv, N_NODES, K);
    aggr_k<<<(N_NODES * 4 * 32 + 255) / 256, 256>>>(hbuf, bias, out, do_round);
}

extern "C" void kernel_launch(void* const* d_in, const int* in_sizes, int n_in,
                              void* d_out, int out_size)
{
    const float* inp = (const float*)d_in[0];
    const int*   ei  = (const int*)d_in[1];
    const float* W1  = (const float*)d_in[2];
    const float* as1 = (const float*)d_in[3];
    const float* ad1 = (const float*)d_in[4];
    const float* b1  = (const float*)d_in[5];
    const float* W2  = (const float*)d_in[6];
    const float* as2 = (const float*)d_in[7];
    const float* ad2 = (const float*)d_in[8];
    const float* b2  = (const float*)d_in[9];
    const float* W3  = (const float*)d_in[10];
    const float* as3 = (const float*)d_in[11];
    const float* ad3 = (const float*)d_in[12];
    const float* b3  = (const float*)d_in[13];
    float* out = (float*)d_out;

    float *hbuf, *xbuf, *bt1, *bt2, *bt3;
    cudaGetSymbolAddress((void**)&hbuf, g_h);
    cudaGetSymbolAddress((void**)&xbuf, g_x);
    cudaGetSymbolAddress((void**)&bt1, g_bt1);
    cudaGetSymbolAddress((void**)&bt2, g_bt2);
    cudaGetSymbolAddress((void**)&bt3, g_bt3);

    cudaFuncSetAttribute(gemm_mma, cudaFuncAttributeMaxDynamicSharedMemorySize, GEMM_SMEM);

    // CSR build (constant across layers)
    zero_counts_k<<<(N_NODES + 255) / 256, 256>>>();
    hist_k<<<(E_TOT + 255) / 256, 256>>>(ei);
    scan_k<<<1, 1024>>>();
    scatter_k<<<(E_TOT + 255) / 256, 256>>>(ei);

    // weight transposes (tf32-rounded) + rounded input activations
    transpose_rnd_k<<<(256 * 128 + 255) / 256, 256>>>(W1, bt1, 128);
    transpose_rnd_k<<<(256 * 256 + 255) / 256, 256>>>(W2, bt2, 256);
    transpose_rnd_k<<<(256 * 256 + 255) / 256, 256>>>(W3, bt3, 256);
    round_k<<<(N_NODES * 128 + 255) / 256, 256>>>(inp, xbuf, N_NODES * 128);

    run_layer(xbuf, 128, bt1, as1, ad1, b1, hbuf, xbuf, 1);
    run_layer(xbuf, 256, bt2, as2, ad2, b2, hbuf, xbuf, 1);
    run_layer(xbuf, 256, bt3, as3, ad3, b3, hbuf, out, 0);
}

// round 5
// speedup vs baseline: 2.0392x; 1.2410x over previous
#include <cuda_runtime.h>
#include <cstdint>

#define N_NODES 50000
#define N_EDGES 800000
#define E_TOT   (N_EDGES + N_NODES)
#define NCOLS   256
#define SLOPE   0.2f

// ---------------- scratch (device globals) -----------------------------------
__device__ float g_h[N_NODES * NCOLS];
__device__ float g_x[N_NODES * NCOLS];
__device__ float g_bt1[256 * 128];     // W^T, tf32-rounded, [n][k]
__device__ float g_bt2[256 * 256];
__device__ float g_bt3[256 * 256];
__device__ float g_asrc[N_NODES * 4];
__device__ float g_adst[N_NODES * 4];
__device__ int   g_counts[N_NODES];
__device__ int   g_rowptr[N_NODES + 1];
__device__ int   g_cursor[N_NODES];
__device__ int   g_csr_src[E_TOT];

__device__ __forceinline__ float tf32r(float x) {
    float y;
    asm("cvt.rna.tf32.f32 %0, %1;" : "=f"(y) : "f"(x));
    return y;
}
__device__ __forceinline__ void cpa16(uint32_t sdst, const void* gsrc, int srcsize) {
    asm volatile("cp.async.cg.shared.global [%0], [%1], 16, %2;"
                 :: "r"(sdst), "l"(gsrc), "r"(srcsize));
}
__device__ __forceinline__ float comp4(float4 v, int i) {
    float r = v.x;
    r = (i == 1) ? v.y : r;
    r = (i == 2) ? v.z : r;
    r = (i == 3) ? v.w : r;
    return r;
}

// ---------------- CSR build ----------------------------------------------------
__global__ void zero_counts_k() {
    int i = blockIdx.x * blockDim.x + threadIdx.x;
    if (i < N_NODES) g_counts[i] = 0;
}
__global__ void hist_k(const int* __restrict__ ei) {
    int e = blockIdx.x * blockDim.x + threadIdx.x;
    if (e < E_TOT) {
        int d = (e < N_EDGES) ? ei[N_EDGES + e] : (e - N_EDGES);
        atomicAdd(&g_counts[d], 1);
    }
}
__global__ void scan_k() {
    __shared__ int sums[1024];
    int tid = threadIdx.x;
    const int chunk = (N_NODES + 1023) / 1024;
    int start = tid * chunk;
    int end = min(start + chunk, N_NODES);
    int s = 0;
    for (int i = start; i < end; i++) s += g_counts[i];
    sums[tid] = s;
    __syncthreads();
    for (int d = 1; d < 1024; d <<= 1) {
        int v = (tid >= d) ? sums[tid - d] : 0;
        __syncthreads();
        sums[tid] += v;
        __syncthreads();
    }
    int off = sums[tid] - s;
    for (int i = start; i < end; i++) {
        g_rowptr[i] = off;
        g_cursor[i] = off;
        off += g_counts[i];
    }
    if (end == N_NODES) g_rowptr[N_NODES] = off;
}
__global__ void scatter_k(const int* __restrict__ ei) {
    int e = blockIdx.x * blockDim.x + threadIdx.x;
    if (e < E_TOT) {
        int s, d;
        if (e < N_EDGES) { s = ei[e]; d = ei[N_EDGES + e]; }
        else             { s = d = e - N_EDGES; }
        int pos = atomicAdd(&g_cursor[d], 1);
        g_csr_src[pos] = s;
    }
}

// ---------------- prep kernels ---------------------------------------------------
__global__ void transpose_rnd_k(const float* __restrict__ W, float* __restrict__ Bt, int K) {
    int idx = blockIdx.x * blockDim.x + threadIdx.x;
    if (idx >= 256 * K) return;
    int n = idx / K, k = idx - n * K;
    Bt[idx] = tf32r(W[k * 256 + n]);
}
__global__ void round_k(const float* __restrict__ in, float* __restrict__ o, int n) {
    int i = blockIdx.x * blockDim.x + threadIdx.x;
    if (i < n) o[i] = tf32r(in[i]);
}

// ---------------- cp.async db tf32 GEMM, tile 128x256, fused alpha ---------------
#define SMS 36
#define TILE_AF (128 * SMS)
#define TILE_BF (256 * SMS)
#define GEMM_SMEM ((TILE_AF + TILE_BF) * 2 * 4)   // 110592 B

__global__ __launch_bounds__(256, 1) void gemm_mma(
    const float* __restrict__ A, const float* __restrict__ Bt,
    float* __restrict__ C,
    const float* __restrict__ avs, const float* __restrict__ avd,
    int M, int K)
{
    extern __shared__ float sm[];
    float* Abuf = sm;                    // [2][TILE_AF]
    float* Bbuf = sm + 2 * TILE_AF;      // [2][TILE_BF]
    uint32_t sA0 = (uint32_t)__cvta_generic_to_shared(Abuf);
    uint32_t sB0 = (uint32_t)__cvta_generic_to_shared(Bbuf);

    int t = threadIdx.x;
    int lane = t & 31, wid = t >> 5;
    int wm = wid & 1, wn = wid >> 1;     // 2 x 4 warp grid
    int g = lane >> 2, tg = lane & 3;
    int row0 = blockIdx.x * 128;

    const int nch = K >> 5;

    auto issue = [&](int kc, int buf) {
        int k0 = kc << 5;
        uint32_t sa = sA0 + buf * (TILE_AF * 4);
        uint32_t sb = sB0 + buf * (TILE_BF * 4);
#pragma unroll
        for (int i = 0; i < 4; i++) {            // A: 128 rows x 8 float4
            int idx = t + (i << 8);
            int r = idx >> 3, c16 = (idx & 7) << 2;
            int gr = row0 + r;
            const float* srcA = A + (size_t)min(gr, M - 1) * K + k0 + c16;
            cpa16(sa + (r * SMS + c16) * 4, srcA, gr < M ? 16 : 0);
        }
#pragma unroll
        for (int i = 0; i < 8; i++) {            // B: 256 rows x 8 float4
            int idx = t + (i << 8);
            int r = idx >> 3, c16 = (idx & 7) << 2;
            const float* srcB = Bt + (size_t)r * K + k0 + c16;
            cpa16(sb + (r * SMS + c16) * 4, srcB, 16);
        }
        asm volatile("cp.async.commit_group;" ::: "memory");
    };

    float c[4][8][4] = {};
    issue(0, 0);

    for (int kc = 0; kc < nch; kc++) {
        int buf = kc & 1;
        if (kc + 1 < nch) {
            issue(kc + 1, buf ^ 1);
            asm volatile("cp.async.wait_group 1;" ::: "memory");
        } else {
            asm volatile("cp.async.wait_group 0;" ::: "memory");
        }
        __syncthreads();
        const float* Ab = Abuf + buf * TILE_AF;
        const float* Bb = Bbuf + buf * TILE_BF;
#pragma unroll
        for (int ks = 0; ks < 4; ks++) {
            int kb = ks * 8;
            uint32_t a[4][4], b[8][2];
#pragma unroll
            for (int mf = 0; mf < 4; mf++) {
                int r = wm * 64 + mf * 16 + g;
                a[mf][0] = __float_as_uint(Ab[r * SMS + kb + tg]);
                a[mf][1] = __float_as_uint(Ab[(r + 8) * SMS + kb + tg]);
                a[mf][2] = __float_as_uint(Ab[r * SMS + kb + tg + 4]);
                a[mf][3] = __float_as_uint(Ab[(r + 8) * SMS + kb + tg + 4]);
            }
#pragma unroll
            for (int nf = 0; nf < 8; nf++) {
                int n = wn * 64 + nf * 8 + g;
                b[nf][0] = __float_as_uint(Bb[n * SMS + kb + tg]);
                b[nf][1] = __float_as_uint(Bb[n * SMS + kb + tg + 4]);
            }
#pragma unroll
            for (int mf = 0; mf < 4; mf++)
#pragma unroll
                for (int nf = 0; nf < 8; nf++)
                    asm volatile(
                        "mma.sync.aligned.m16n8k8.row.col.f32.tf32.tf32.f32 "
                        "{%0,%1,%2,%3}, {%4,%5,%6,%7}, {%8,%9}, {%0,%1,%2,%3};"
                        : "+f"(c[mf][nf][0]), "+f"(c[mf][nf][1]),
                          "+f"(c[mf][nf][2]), "+f"(c[mf][nf][3])
                        : "r"(a[mf][0]), "r"(a[mf][1]), "r"(a[mf][2]), "r"(a[mf][3]),
                          "r"(b[nf][0]), "r"(b[nf][1]));
        }
        __syncthreads();
    }

    // epilogue: store C + fused attention dots (warp column band = one head)
    int head = wn;
#pragma unroll
    for (int mf = 0; mf < 4; mf++) {
        int r0 = row0 + wm * 64 + mf * 16 + g;
        int r1 = r0 + 8;
        float sv0 = 0.f, sv1 = 0.f, dv0 = 0.f, dv1 = 0.f;
#pragma unroll
        for (int nf = 0; nf < 8; nf++) {
            int col = wn * 64 + nf * 8 + tg * 2;
            float x0 = c[mf][nf][0], x1 = c[mf][nf][1];
            float x2 = c[mf][nf][2], x3 = c[mf][nf][3];
            if (r0 < M) *(float2*)(C + (size_t)r0 * NCOLS + col) = make_float2(x0, x1);
            if (r1 < M) *(float2*)(C + (size_t)r1 * NCOLS + col) = make_float2(x2, x3);
            float w0 = __ldg(avs + col), w1 = __ldg(avs + col + 1);
            float u0 = __ldg(avd + col), u1 = __ldg(avd + col + 1);
            sv0 += x0 * w0 + x1 * w1;
            sv1 += x2 * w0 + x3 * w1;
            dv0 += x0 * u0 + x1 * u1;
            dv1 += x2 * u0 + x3 * u1;
        }
        sv0 += __shfl_xor_sync(0xffffffffu, sv0, 1);
        sv0 += __shfl_xor_sync(0xffffffffu, sv0, 2);
        sv1 += __shfl_xor_sync(0xffffffffu, sv1, 1);
        sv1 += __shfl_xor_sync(0xffffffffu, sv1, 2);
        dv0 += __shfl_xor_sync(0xffffffffu, dv0, 1);
        dv0 += __shfl_xor_sync(0xffffffffu, dv0, 2);
        dv1 += __shfl_xor_sync(0xffffffffu, dv1, 1);
        dv1 += __shfl_xor_sync(0xffffffffu, dv1, 2);
        if (tg == 0) {
            if (r0 < M) { g_asrc[r0 * 4 + head] = sv0; g_adst[r0 * 4 + head] = dv0; }
            if (r1 < M) { g_asrc[r1 * 4 + head] = sv1; g_adst[r1 * 4 + head] = dv1; }
        }
    }
}

// ---------------- aggregation: one warp per dst, all 4 heads --------------------
// lane owns channels [lane*8, lane*8+8)  (head = lane>>3)
__global__ __launch_bounds__(256) void aggr_k(
    const float* __restrict__ h, const float* __restrict__ bias,
    float* __restrict__ out, int do_round)
{
    __shared__ float sw[8][128];   // per-warp chunk weights [edge][head]
    int d    = (blockIdx.x * blockDim.x + threadIdx.x) >> 5;
    int lane = threadIdx.x & 31;
    int wblk = threadIdx.x >> 5;
    if (d >= N_NODES) return;
    int hol = lane >> 3;
    float* swp = sw[wblk];

    int beg = g_rowptr[d];
    int end = g_rowptr[d + 1];
    float4 adst4 = *(const float4*)(g_adst + d * 4);

    float4 m4 = make_float4(-1e30f, -1e30f, -1e30f, -1e30f);
    float4 ssum4 = make_float4(0.f, 0.f, 0.f, 0.f);
    float4 acc0 = make_float4(0.f, 0.f, 0.f, 0.f);
    float4 acc1 = make_float4(0.f, 0.f, 0.f, 0.f);

    for (int base = beg; base < end; base += 32) {
        int i = base + lane;
        bool v = i < end;
        int s_l = v ? g_csr_src[i] : 0;
        float4 e4 = make_float4(-1e30f, -1e30f, -1e30f, -1e30f);
        if (v) {
            float4 as4 = *(const float4*)(g_asrc + s_l * 4);
            float ex = as4.x + adst4.x, ey = as4.y + adst4.y;
            float ez = as4.z + adst4.z, ew = as4.w + adst4.w;
            e4.x = ex > 0.f ? ex : SLOPE * ex;
            e4.y = ey > 0.f ? ey : SLOPE * ey;
            e4.z = ez > 0.f ? ez : SLOPE * ez;
            e4.w = ew > 0.f ? ew : SLOPE * ew;
        }
        // chunk max per head
        float4 cm = e4;
#pragma unroll
        for (int o = 16; o; o >>= 1) {
            cm.x = fmaxf(cm.x, __shfl_xor_sync(0xffffffffu, cm.x, o));
            cm.y = fmaxf(cm.y, __shfl_xor_sync(0xffffffffu, cm.y, o));
            cm.z = fmaxf(cm.z, __shfl_xor_sync(0xffffffffu, cm.z, o));
            cm.w = fmaxf(cm.w, __shfl_xor_sync(0xffffffffu, cm.w, o));
        }
        float4 mn = make_float4(fmaxf(m4.x, cm.x), fmaxf(m4.y, cm.y),
                                fmaxf(m4.z, cm.z), fmaxf(m4.w, cm.w));
        float4 sc = make_float4(__expf(m4.x - mn.x), __expf(m4.y - mn.y),
                                __expf(m4.z - mn.z), __expf(m4.w - mn.w));
        m4 = mn;
        ssum4.x *= sc.x; ssum4.y *= sc.y; ssum4.z *= sc.z; ssum4.w *= sc.w;
        float scl = comp4(sc, hol);
        acc0.x *= scl; acc0.y *= scl; acc0.z *= scl; acc0.w *= scl;
        acc1.x *= scl; acc1.y *= scl; acc1.z *= scl; acc1.w *= scl;

        float4 w4 = make_float4(0.f, 0.f, 0.f, 0.f);
        if (v) {
            w4.x = __expf(e4.x - m4.x);
            w4.y = __expf(e4.y - m4.y);
            w4.z = __expf(e4.z - m4.z);
            w4.w = __expf(e4.w - m4.w);
        }
        float4 ws = w4;
#pragma unroll
        for (int o = 16; o; o >>= 1) {
            ws.x += __shfl_xor_sync(0xffffffffu, ws.x, o);
            ws.y += __shfl_xor_sync(0xffffffffu, ws.y, o);
            ws.z += __shfl_xor_sync(0xffffffffu, ws.z, o);
            ws.w += __shfl_xor_sync(0xffffffffu, ws.w, o);
        }
        ssum4.x += ws.x; ssum4.y += ws.y; ssum4.z += ws.z; ssum4.w += ws.w;

        *(float4*)(swp + lane * 4) = w4;
        __syncwarp();

        int n = min(32, end - base);
        int j = 0;
        for (; j + 2 <= n; j += 2) {
            int s0 = __shfl_sync(0xffffffffu, s_l, j);
            int s1 = __shfl_sync(0xffffffffu, s_l, j + 1);
            float w0 = swp[j * 4 + hol];
            float w1 = swp[j * 4 + 4 + hol];
            const float4* h0 = (const float4*)(h + (size_t)s0 * NCOLS + lane * 8);
            const float4* h1 = (const float4*)(h + (size_t)s1 * NCOLS + lane * 8);
            float4 p0 = h0[0], p1 = h0[1];
            float4 q0 = h1[0], q1 = h1[1];
            acc0.x += w0 * p0.x + w1 * q0.x;
            acc0.y += w0 * p0.y + w1 * q0.y;
            acc0.z += w0 * p0.z + w1 * q0.z;
            acc0.w += w0 * p0.w + w1 * q0.w;
            acc1.x += w0 * p1.x + w1 * q1.x;
            acc1.y += w0 * p1.y + w1 * q1.y;
            acc1.z += w0 * p1.z + w1 * q1.z;
            acc1.w += w0 * p1.w + w1 * q1.w;
        }
        if (j < n) {
            int s0 = __shfl_sync(0xffffffffu, s_l, j);
            float w0 = swp[j * 4 + hol];
            const float4* h0 = (const float4*)(h + (size_t)s0 * NCOLS + lane * 8);
            float4 p0 = h0[0], p1 = h0[1];
            acc0.x += w0 * p0.x; acc0.y += w0 * p0.y;
            acc0.z += w0 * p0.z; acc0.w += w0 * p0.w;
            acc1.x += w0 * p1.x; acc1.y += w0 * p1.y;
            acc1.z += w0 * p1.z; acc1.w += w0 * p1.w;
        }
        __syncwarp();
    }

    float inv = 1.f / comp4(ssum4, hol);
    int c0 = lane * 8;
    float4 bb0 = *(const float4*)(bias + c0);
    float4 bb1 = *(const float4*)(bias + c0 + 4);
    float o_[8];
    o_[0] = acc0.x * inv + bb0.x; o_[1] = acc0.y * inv + bb0.y;
    o_[2] = acc0.z * inv + bb0.z; o_[3] = acc0.w * inv + bb0.w;
    o_[4] = acc1.x * inv + bb1.x; o_[5] = acc1.y * inv + bb1.y;
    o_[6] = acc1.z * inv + bb1.z; o_[7] = acc1.w * inv + bb1.w;
#pragma unroll
    for (int k = 0; k < 8; k++) {
        float o = o_[k];
        o = o > 0.f ? o : (__expf(o) - 1.f);
        if (do_round) o = tf32r(o);
        o_[k] = o;
    }
    *(float4*)(out + (size_t)d * NCOLS + c0)     = make_float4(o_[0], o_[1], o_[2], o_[3]);
    *(float4*)(out + (size_t)d * NCOLS + c0 + 4) = make_float4(o_[4], o_[5], o_[6], o_[7]);
}

// ---------------- driver ---------------------------------------------------------
static void run_layer(const float* x, int K, const float* bt,
                      const float* asv, const float* adv, const float* bias,
                      float* hbuf, float* out, int do_round)
{
    gemm_mma<<<(N_NODES + 127) / 128, 256, GEMM_SMEM>>>(x, bt, hbuf, asv, adv, N_NODES, K);
    aggr_k<<<(N_NODES * 32 + 255) / 256, 256>>>(hbuf, bias, out, do_round);
}

extern "C" void kernel_launch(void* const* d_in, const int* in_sizes, int n_in,
                              void* d_out, int out_size)
{
    const float* inp = (const float*)d_in[0];
    const int*   ei  = (const int*)d_in[1];
    const float* W1  = (const float*)d_in[2];
    const float* as1 = (const float*)d_in[3];
    const float* ad1 = (const float*)d_in[4];
    const float* b1  = (const float*)d_in[5];
    const float* W2  = (const float*)d_in[6];
    const float* as2 = (const float*)d_in[7];
    const float* ad2 = (const float*)d_in[8];
    const float* b2  = (const float*)d_in[9];
    const float* W3  = (const float*)d_in[10];
    const float* as3 = (const float*)d_in[11];
    const float* ad3 = (const float*)d_in[12];
    const float* b3  = (const float*)d_in[13];
    float* out = (float*)d_out;

    float *hbuf, *xbuf, *bt1, *bt2, *bt3;
    cudaGetSymbolAddress((void**)&hbuf, g_h);
    cudaGetSymbolAddress((void**)&xbuf, g_x);
    cudaGetSymbolAddress((void**)&bt1, g_bt1);
    cudaGetSymbolAddress((void**)&bt2, g_bt2);
    cudaGetSymbolAddress((void**)&bt3, g_bt3);

    cudaFuncSetAttribute(gemm_mma, cudaFuncAttributeMaxDynamicSharedMemorySize, GEMM_SMEM);

    // CSR build (constant across layers)
    zero_counts_k<<<(N_NODES + 255) / 256, 256>>>();
    hist_k<<<(E_TOT + 255) / 256, 256>>>(ei);
    scan_k<<<1, 1024>>>();
    scatter_k<<<(E_TOT + 255) / 256, 256>>>(ei);

    // weight transposes (tf32-rounded) + rounded input activations
    transpose_rnd_k<<<(256 * 128 + 255) / 256, 256>>>(W1, bt1, 128);
    transpose_rnd_k<<<(256 * 256 + 255) / 256, 256>>>(W2, bt2, 256);
    transpose_rnd_k<<<(256 * 256 + 255) / 256, 256>>>(W3, bt3, 256);
    round_k<<<(N_NODES * 128 + 255) / 256, 256>>>(inp, xbuf, N_NODES * 128);

    run_layer(xbuf, 128, bt1, as1, ad1, b1, hbuf, xbuf, 1);
    run_layer(xbuf, 256, bt2, as2, ad2, b2, hbuf, xbuf, 1);
    run_layer(xbuf, 256, bt3, as3, ad3, b3, hbuf, out, 0);
}

// round 6
// speedup vs baseline: 2.0678x; 1.0140x over previous
#include <cuda_runtime.h>
#include <cstdint>

#define N_NODES 50000
#define N_EDGES 800000
#define E_TOT   (N_EDGES + N_NODES)
#define NCOLS   256
#define SLOPE   0.2f

// ---------------- scratch (device globals) -----------------------------------
__device__ float g_h[N_NODES * NCOLS];
__device__ float g_x[N_NODES * NCOLS];
__device__ float g_bt1[256 * 128];     // W^T, tf32-rounded, [n][k]
__device__ float g_bt2[256 * 256];
__device__ float g_bt3[256 * 256];
__device__ float g_asrc[N_NODES * 4];
__device__ float g_adst[N_NODES * 4];
__device__ int   g_counts[N_NODES];
__device__ int   g_rowptr[N_NODES + 1];
__device__ int   g_cursor[N_NODES];
__device__ int   g_csr_src[E_TOT];

__device__ __forceinline__ float tf32r(float x) {
    float y;
    asm("cvt.rna.tf32.f32 %0, %1;" : "=f"(y) : "f"(x));
    return y;
}
__device__ __forceinline__ void cpa16(uint32_t sdst, const void* gsrc, int srcsize) {
    asm volatile("cp.async.cg.shared.global [%0], [%1], 16, %2;"
                 :: "r"(sdst), "l"(gsrc), "r"(srcsize));
}
__device__ __forceinline__ float comp4(float4 v, int i) {
    float r = v.x;
    r = (i == 1) ? v.y : r;
    r = (i == 2) ? v.z : r;
    r = (i == 3) ? v.w : r;
    return r;
}

// ---------------- CSR build ----------------------------------------------------
__global__ void zero_counts_k() {
    int i = blockIdx.x * blockDim.x + threadIdx.x;
    if (i < N_NODES) g_counts[i] = 0;
}
__global__ void hist_k(const int* __restrict__ ei) {
    int e = blockIdx.x * blockDim.x + threadIdx.x;
    if (e < E_TOT) {
        int d = (e < N_EDGES) ? ei[N_EDGES + e] : (e - N_EDGES);
        atomicAdd(&g_counts[d], 1);
    }
}
__global__ void scan_k() {
    __shared__ int sums[1024];
    int tid = threadIdx.x;
    const int chunk = (N_NODES + 1023) / 1024;
    int start = tid * chunk;
    int end = min(start + chunk, N_NODES);
    int s = 0;
    for (int i = start; i < end; i++) s += g_counts[i];
    sums[tid] = s;
    __syncthreads();
    for (int d = 1; d < 1024; d <<= 1) {
        int v = (tid >= d) ? sums[tid - d] : 0;
        __syncthreads();
        sums[tid] += v;
        __syncthreads();
    }
    int off = sums[tid] - s;
    for (int i = start; i < end; i++) {
        g_rowptr[i] = off;
        g_cursor[i] = off;
        off += g_counts[i];
    }
    if (end == N_NODES) g_rowptr[N_NODES] = off;
}
__global__ void scatter_k(const int* __restrict__ ei) {
    int e = blockIdx.x * blockDim.x + threadIdx.x;
    if (e < E_TOT) {
        int s, d;
        if (e < N_EDGES) { s = ei[e]; d = ei[N_EDGES + e]; }
        else             { s = d = e - N_EDGES; }
        int pos = atomicAdd(&g_cursor[d], 1);
        g_csr_src[pos] = s;
    }
}

// ---------------- prep kernels ---------------------------------------------------
__global__ void transpose_rnd_k(const float* __restrict__ W, float* __restrict__ Bt, int K) {
    int idx = blockIdx.x * blockDim.x + threadIdx.x;
    if (idx >= 256 * K) return;
    int n = idx / K, k = idx - n * K;
    Bt[idx] = tf32r(W[k * 256 + n]);
}
__global__ void round_k(const float* __restrict__ in, float* __restrict__ o, int n) {
    int i = blockIdx.x * blockDim.x + threadIdx.x;
    if (i < n) o[i] = tf32r(in[i]);
}

// ---------------- 3-stage cp.async tf32 GEMM, tile 128x256, fused alpha ----------
#define SMS 36
#define TILE_AF (128 * SMS)
#define TILE_BF (256 * SMS)
#define STAGES 3
#define GEMM_SMEM (STAGES * (TILE_AF + TILE_BF) * 4)   // 165888 B

__global__ __launch_bounds__(256, 1) void gemm_mma(
    const float* __restrict__ A, const float* __restrict__ Bt,
    float* __restrict__ C,
    const float* __restrict__ avs, const float* __restrict__ avd,
    int M, int K)
{
    extern __shared__ float sm[];
    float* Abuf = sm;                          // [STAGES][TILE_AF]
    float* Bbuf = sm + STAGES * TILE_AF;       // [STAGES][TILE_BF]
    uint32_t sA0 = (uint32_t)__cvta_generic_to_shared(Abuf);
    uint32_t sB0 = (uint32_t)__cvta_generic_to_shared(Bbuf);

    int t = threadIdx.x;
    int lane = t & 31, wid = t >> 5;
    int wm = wid & 1, wn = wid >> 1;     // 2 x 4 warp grid
    int g = lane >> 2, tg = lane & 3;
    int row0 = blockIdx.x * 128;

    const int nch = K >> 5;

    auto issue = [&](int kc, int stg) {
        int k0 = kc << 5;
        uint32_t sa = sA0 + stg * (TILE_AF * 4);
        uint32_t sb = sB0 + stg * (TILE_BF * 4);
#pragma unroll
        for (int i = 0; i < 4; i++) {            // A: 128 rows x 8 float4
            int idx = t + (i << 8);
            int r = idx >> 3, c16 = (idx & 7) << 2;
            int gr = row0 + r;
            const float* srcA = A + (size_t)min(gr, M - 1) * K + k0 + c16;
            cpa16(sa + (r * SMS + c16) * 4, srcA, gr < M ? 16 : 0);
        }
#pragma unroll
        for (int i = 0; i < 8; i++) {            // B: 256 rows x 8 float4
            int idx = t + (i << 8);
            int r = idx >> 3, c16 = (idx & 7) << 2;
            const float* srcB = Bt + (size_t)r * K + k0 + c16;
            cpa16(sb + (r * SMS + c16) * 4, srcB, 16);
        }
        asm volatile("cp.async.commit_group;" ::: "memory");
    };

    float c[4][8][4] = {};
    issue(0, 0);
    issue(1, 1);

    for (int kc = 0; kc < nch; kc++) {
        int stg = kc % STAGES;
        if (kc + 2 < nch) {
            issue(kc + 2, (kc + 2) % STAGES);
            asm volatile("cp.async.wait_group 2;" ::: "memory");
        } else if (kc + 1 < nch) {
            asm volatile("cp.async.wait_group 1;" ::: "memory");
        } else {
            asm volatile("cp.async.wait_group 0;" ::: "memory");
        }
        __syncthreads();
        const float* Ab = Abuf + stg * TILE_AF;
        const float* Bb = Bbuf + stg * TILE_BF;
#pragma unroll
        for (int ks = 0; ks < 4; ks++) {
            int kb = ks * 8;
            uint32_t a[4][4], b[8][2];
#pragma unroll
            for (int mf = 0; mf < 4; mf++) {
                int r = wm * 64 + mf * 16 + g;
                a[mf][0] = __float_as_uint(Ab[r * SMS + kb + tg]);
                a[mf][1] = __float_as_uint(Ab[(r + 8) * SMS + kb + tg]);
                a[mf][2] = __float_as_uint(Ab[r * SMS + kb + tg + 4]);
                a[mf][3] = __float_as_uint(Ab[(r + 8) * SMS + kb + tg + 4]);
            }
#pragma unroll
            for (int nf = 0; nf < 8; nf++) {
                int n = wn * 64 + nf * 8 + g;
                b[nf][0] = __float_as_uint(Bb[n * SMS + kb + tg]);
                b[nf][1] = __float_as_uint(Bb[n * SMS + kb + tg + 4]);
            }
#pragma unroll
            for (int mf = 0; mf < 4; mf++)
#pragma unroll
                for (int nf = 0; nf < 8; nf++)
                    asm volatile(
                        "mma.sync.aligned.m16n8k8.row.col.f32.tf32.tf32.f32 "
                        "{%0,%1,%2,%3}, {%4,%5,%6,%7}, {%8,%9}, {%0,%1,%2,%3};"
                        : "+f"(c[mf][nf][0]), "+f"(c[mf][nf][1]),
                          "+f"(c[mf][nf][2]), "+f"(c[mf][nf][3])
                        : "r"(a[mf][0]), "r"(a[mf][1]), "r"(a[mf][2]), "r"(a[mf][3]),
                          "r"(b[nf][0]), "r"(b[nf][1]));
        }
        __syncthreads();
    }

    // epilogue: store C + fused attention dots (warp column band = one head)
    int head = wn;
#pragma unroll
    for (int mf = 0; mf < 4; mf++) {
        int r0 = row0 + wm * 64 + mf * 16 + g;
        int r1 = r0 + 8;
        float sv0 = 0.f, sv1 = 0.f, dv0 = 0.f, dv1 = 0.f;
#pragma unroll
        for (int nf = 0; nf < 8; nf++) {
            int col = wn * 64 + nf * 8 + tg * 2;
            float x0 = c[mf][nf][0], x1 = c[mf][nf][1];
            float x2 = c[mf][nf][2], x3 = c[mf][nf][3];
            if (r0 < M) *(float2*)(C + (size_t)r0 * NCOLS + col) = make_float2(x0, x1);
            if (r1 < M) *(float2*)(C + (size_t)r1 * NCOLS + col) = make_float2(x2, x3);
            float w0 = __ldg(avs + col), w1 = __ldg(avs + col + 1);
            float u0 = __ldg(avd + col), u1 = __ldg(avd + col + 1);
            sv0 += x0 * w0 + x1 * w1;
            sv1 += x2 * w0 + x3 * w1;
            dv0 += x0 * u0 + x1 * u1;
            dv1 += x2 * u0 + x3 * u1;
        }
        sv0 += __shfl_xor_sync(0xffffffffu, sv0, 1);
        sv0 += __shfl_xor_sync(0xffffffffu, sv0, 2);
        sv1 += __shfl_xor_sync(0xffffffffu, sv1, 1);
        sv1 += __shfl_xor_sync(0xffffffffu, sv1, 2);
        dv0 += __shfl_xor_sync(0xffffffffu, dv0, 1);
        dv0 += __shfl_xor_sync(0xffffffffu, dv0, 2);
        dv1 += __shfl_xor_sync(0xffffffffu, dv1, 1);
        dv1 += __shfl_xor_sync(0xffffffffu, dv1, 2);
        if (tg == 0) {
            if (r0 < M) { g_asrc[r0 * 4 + head] = sv0; g_adst[r0 * 4 + head] = dv0; }
            if (r1 < M) { g_asrc[r1 * 4 + head] = sv1; g_adst[r1 * 4 + head] = dv1; }
        }
    }
}

// ---------------- aggregation: one warp per dst, all 4 heads --------------------
// lane owns channels [lane*8, lane*8+8)  (head = lane>>3)
__global__ __launch_bounds__(256) void aggr_k(
    const float* __restrict__ h, const float* __restrict__ bias,
    float* __restrict__ out, int do_round)
{
    __shared__ float sw[8][128];   // per-warp chunk weights [edge][head]
    int d    = (blockIdx.x * blockDim.x + threadIdx.x) >> 5;
    int lane = threadIdx.x & 31;
    int wblk = threadIdx.x >> 5;
    if (d >= N_NODES) return;
    int hol = lane >> 3;
    float* swp = sw[wblk];

    int beg = g_rowptr[d];
    int end = g_rowptr[d + 1];
    float4 adst4 = *(const float4*)(g_adst + d * 4);

    float4 m4 = make_float4(-1e30f, -1e30f, -1e30f, -1e30f);
    float4 ssum4 = make_float4(0.f, 0.f, 0.f, 0.f);
    float4 acc0 = make_float4(0.f, 0.f, 0.f, 0.f);
    float4 acc1 = make_float4(0.f, 0.f, 0.f, 0.f);

    for (int base = beg; base < end; base += 32) {
        int i = base + lane;
        bool v = i < end;
        int s_l = v ? g_csr_src[i] : 0;
        float4 e4 = make_float4(-1e30f, -1e30f, -1e30f, -1e30f);
        if (v) {
            float4 as4 = *(const float4*)(g_asrc + s_l * 4);
            float ex = as4.x + adst4.x, ey = as4.y + adst4.y;
            float ez = as4.z + adst4.z, ew = as4.w + adst4.w;
            e4.x = ex > 0.f ? ex : SLOPE * ex;
            e4.y = ey > 0.f ? ey : SLOPE * ey;
            e4.z = ez > 0.f ? ez : SLOPE * ez;
            e4.w = ew > 0.f ? ew : SLOPE * ew;
        }
        float4 cm = e4;
#pragma unroll
        for (int o = 16; o; o >>= 1) {
            cm.x = fmaxf(cm.x, __shfl_xor_sync(0xffffffffu, cm.x, o));
            cm.y = fmaxf(cm.y, __shfl_xor_sync(0xffffffffu, cm.y, o));
            cm.z = fmaxf(cm.z, __shfl_xor_sync(0xffffffffu, cm.z, o));
            cm.w = fmaxf(cm.w, __shfl_xor_sync(0xffffffffu, cm.w, o));
        }
        float4 mn = make_float4(fmaxf(m4.x, cm.x), fmaxf(m4.y, cm.y),
                                fmaxf(m4.z, cm.z), fmaxf(m4.w, cm.w));
        float4 sc = make_float4(__expf(m4.x - mn.x), __expf(m4.y - mn.y),
                                __expf(m4.z - mn.z), __expf(m4.w - mn.w));
        m4 = mn;
        ssum4.x *= sc.x; ssum4.y *= sc.y; ssum4.z *= sc.z; ssum4.w *= sc.w;
        float scl = comp4(sc, hol);
        acc0.x *= scl; acc0.y *= scl; acc0.z *= scl; acc0.w *= scl;
        acc1.x *= scl; acc1.y *= scl; acc1.z *= scl; acc1.w *= scl;

        float4 w4 = make_float4(0.f, 0.f, 0.f, 0.f);
        if (v) {
            w4.x = __expf(e4.x - m4.x);
            w4.y = __expf(e4.y - m4.y);
            w4.z = __expf(e4.z - m4.z);
            w4.w = __expf(e4.w - m4.w);
        }
        float4 ws = w4;
#pragma unroll
        for (int o = 16; o; o >>= 1) {
            ws.x += __shfl_xor_sync(0xffffffffu, ws.x, o);
            ws.y += __shfl_xor_sync(0xffffffffu, ws.y, o);
            ws.z += __shfl_xor_sync(0xffffffffu, ws.z, o);
            ws.w += __shfl_xor_sync(0xffffffffu, ws.w, o);
        }
        ssum4.x += ws.x; ssum4.y += ws.y; ssum4.z += ws.z; ssum4.w += ws.w;

        *(float4*)(swp + lane * 4) = w4;
        __syncwarp();

        int n = min(32, end - base);
        int j = 0;
        for (; j + 4 <= n; j += 4) {
            int s0 = __shfl_sync(0xffffffffu, s_l, j);
            int s1 = __shfl_sync(0xffffffffu, s_l, j + 1);
            int s2 = __shfl_sync(0xffffffffu, s_l, j + 2);
            int s3 = __shfl_sync(0xffffffffu, s_l, j + 3);
            float w0 = swp[j * 4 + hol];
            float w1 = swp[j * 4 + 4 + hol];
            float w2 = swp[j * 4 + 8 + hol];
            float w3 = swp[j * 4 + 12 + hol];
            const float4* h0 = (const float4*)(h + (size_t)s0 * NCOLS + lane * 8);
            const float4* h1 = (const float4*)(h + (size_t)s1 * NCOLS + lane * 8);
            const float4* h2 = (const float4*)(h + (size_t)s2 * NCOLS + lane * 8);
            const float4* h3 = (const float4*)(h + (size_t)s3 * NCOLS + lane * 8);
            float4 p0 = h0[0], p1 = h0[1];
            float4 q0 = h1[0], q1 = h1[1];
            float4 r0 = h2[0], r1 = h2[1];
            float4 t0 = h3[0], t1 = h3[1];
            acc0.x += w0 * p0.x + w1 * q0.x + w2 * r0.x + w3 * t0.x;
            acc0.y += w0 * p0.y + w1 * q0.y + w2 * r0.y + w3 * t0.y;
            acc0.z += w0 * p0.z + w1 * q0.z + w2 * r0.z + w3 * t0.z;
            acc0.w += w0 * p0.w + w1 * q0.w + w2 * r0.w + w3 * t0.w;
            acc1.x += w0 * p1.x + w1 * q1.x + w2 * r1.x + w3 * t1.x;
            acc1.y += w0 * p1.y + w1 * q1.y + w2 * r1.y + w3 * t1.y;
            acc1.z += w0 * p1.z + w1 * q1.z + w2 * r1.z + w3 * t1.z;
            acc1.w += w0 * p1.w + w1 * q1.w + w2 * r1.w + w3 * t1.w;
        }
        for (; j < n; j++) {
            int s0 = __shfl_sync(0xffffffffu, s_l, j);
            float w0 = swp[j * 4 + hol];
            const float4* h0 = (const float4*)(h + (size_t)s0 * NCOLS + lane * 8);
            float4 p0 = h0[0], p1 = h0[1];
            acc0.x += w0 * p0.x; acc0.y += w0 * p0.y;
            acc0.z += w0 * p0.z; acc0.w += w0 * p0.w;
            acc1.x += w0 * p1.x; acc1.y += w0 * p1.y;
            acc1.z += w0 * p1.z; acc1.w += w0 * p1.w;
        }
        __syncwarp();
    }

    float inv = 1.f / comp4(ssum4, hol);
    int c0 = lane * 8;
    float4 bb0 = *(const float4*)(bias + c0);
    float4 bb1 = *(const float4*)(bias + c0 + 4);
    float o_[8];
    o_[0] = acc0.x * inv + bb0.x; o_[1] = acc0.y * inv + bb0.y;
    o_[2] = acc0.z * inv + bb0.z; o_[3] = acc0.w * inv + bb0.w;
    o_[4] = acc1.x * inv + bb1.x; o_[5] = acc1.y * inv + bb1.y;
    o_[6] = acc1.z * inv + bb1.z; o_[7] = acc1.w * inv + bb1.w;
#pragma unroll
    for (int k = 0; k < 8; k++) {
        float o = o_[k];
        o = o > 0.f ? o : (__expf(o) - 1.f);
        if (do_round) o = tf32r(o);
        o_[k] = o;
    }
    *(float4*)(out + (size_t)d * NCOLS + c0)     = make_float4(o_[0], o_[1], o_[2], o_[3]);
    *(float4*)(out + (size_t)d * NCOLS + c0 + 4) = make_float4(o_[4], o_[5], o_[6], o_[7]);
}

// ---------------- driver ---------------------------------------------------------
extern "C" void kernel_launch(void* const* d_in, const int* in_sizes, int n_in,
                              void* d_out, int out_size)
{
    const float* inp = (const float*)d_in[0];
    const int*   ei  = (const int*)d_in[1];
    const float* W1  = (const float*)d_in[2];
    const float* as1 = (const float*)d_in[3];
    const float* ad1 = (const float*)d_in[4];
    const float* b1  = (const float*)d_in[5];
    const float* W2  = (const float*)d_in[6];
    const float* as2 = (const float*)d_in[7];
    const float* ad2 = (const float*)d_in[8];
    const float* b2  = (const float*)d_in[9];
    const float* W3  = (const float*)d_in[10];
    const float* as3 = (const float*)d_in[11];
    const float* ad3 = (const float*)d_in[12];
    const float* b3  = (const float*)d_in[13];
    float* out = (float*)d_out;

    float *hbuf, *xbuf, *bt1, *bt2, *bt3;
    cudaGetSymbolAddress((void**)&hbuf, g_h);
    cudaGetSymbolAddress((void**)&xbuf, g_x);
    cudaGetSymbolAddress((void**)&bt1, g_bt1);
    cudaGetSymbolAddress((void**)&bt2, g_bt2);
    cudaGetSymbolAddress((void**)&bt3, g_bt3);

    cudaFuncSetAttribute(gemm_mma, cudaFuncAttributeMaxDynamicSharedMemorySize, GEMM_SMEM);

    // fork/join resources, created once on the (un-captured) correctness call
    static cudaStream_t s2 = nullptr;
    static cudaEvent_t e_fork = nullptr, e_join = nullptr;
    if (!s2) {
        cudaStreamCreateWithFlags(&s2, cudaStreamNonBlocking);
        cudaEventCreateWithFlags(&e_fork, cudaEventDisableTiming);
        cudaEventCreateWithFlags(&e_join, cudaEventDisableTiming);
    }

    // fork: CSR build on s2 (only gates aggr_k of layer 1)
    cudaEventRecord(e_fork, 0);
    cudaStreamWaitEvent(s2, e_fork, 0);
    zero_counts_k<<<(N_NODES + 255) / 256, 256, 0, s2>>>();
    hist_k<<<(E_TOT + 255) / 256, 256, 0, s2>>>(ei);
    scan_k<<<1, 1024, 0, s2>>>();
    scatter_k<<<(E_TOT + 255) / 256, 256, 0, s2>>>(ei);
    cudaEventRecord(e_join, s2);

    // main stream: weight prep + layer-1 GEMM run concurrently with CSR
    transpose_rnd_k<<<(256 * 128 + 255) / 256, 256>>>(W1, bt1, 128);
    transpose_rnd_k<<<(256 * 256 + 255) / 256, 256>>>(W2, bt2, 256);
    transpose_rnd_k<<<(256 * 256 + 255) / 256, 256>>>(W3, bt3, 256);
    round_k<<<(N_NODES * 128 + 255) / 256, 256>>>(inp, xbuf, N_NODES * 128);

    int ggrid = (N_NODES + 127) / 128;
    int agrid = (N_NODES * 32 + 255) / 256;

    gemm_mma<<<ggrid, 256, GEMM_SMEM>>>(xbuf, bt1, hbuf, as1, ad1, N_NODES, 128);
    cudaStreamWaitEvent(0, e_join, 0);   // join: CSR ready before first aggregation
    aggr_k<<<agrid, 256>>>(hbuf, b1, xbuf, 1);

    gemm_mma<<<ggrid, 256, GEMM_SMEM>>>(xbuf, bt2, hbuf, as2, ad2, N_NODES, 256);
    aggr_k<<<agrid, 256>>>(hbuf, b2, xbuf, 1);

    gemm_mma<<<ggrid, 256, GEMM_SMEM>>>(xbuf, bt3, hbuf, as3, ad3, N_NODES, 256);
    aggr_k<<<agrid, 256>>>(hbuf, b3, out, 0);
}

// round 7
// speedup vs baseline: 2.7122x; 1.3116x over previous
#include <cuda_runtime.h>
#include <cuda_fp16.h>
#include <cstdint>

#define N_NODES 50000
#define N_EDGES 800000
#define E_TOT   (N_EDGES + N_NODES)
#define NCOLS   256
#define SLOPE   0.2f

// ---------------- scratch (device globals) -----------------------------------
__device__ __half g_h[N_NODES * NCOLS];     // GEMM output, fp16 (gather source)
__device__ float  g_x[N_NODES * NCOLS];     // layer activations, fp32
__device__ float  g_bt1[256 * 128];         // W^T, tf32-rounded, [n][k]
__device__ float  g_bt2[256 * 256];
__device__ float  g_bt3[256 * 256];
__device__ float  g_asrc[N_NODES * 4];
__device__ float  g_adst[N_NODES * 4];
__device__ int    g_counts[N_NODES];
__device__ int    g_rowptr[N_NODES + 1];
__device__ int    g_cursor[N_NODES];
__device__ int    g_csr_src[E_TOT];

__device__ __forceinline__ float tf32r(float x) {
    float y;
    asm("cvt.rna.tf32.f32 %0, %1;" : "=f"(y) : "f"(x));
    return y;
}
__device__ __forceinline__ void cpa16(uint32_t sdst, const void* gsrc, int srcsize) {
    asm volatile("cp.async.cg.shared.global [%0], [%1], 16, %2;"
                 :: "r"(sdst), "l"(gsrc), "r"(srcsize));
}
__device__ __forceinline__ float comp4(float4 v, int i) {
    float r = v.x;
    r = (i == 1) ? v.y : r;
    r = (i == 2) ? v.z : r;
    r = (i == 3) ? v.w : r;
    return r;
}

// ---------------- CSR build ----------------------------------------------------
__global__ void zero_counts_k() {
    int i = blockIdx.x * blockDim.x + threadIdx.x;
    if (i < N_NODES) g_counts[i] = 0;
}
__global__ void hist_k(const int* __restrict__ ei) {
    int e = blockIdx.x * blockDim.x + threadIdx.x;
    if (e < E_TOT) {
        int d = (e < N_EDGES) ? ei[N_EDGES + e] : (e - N_EDGES);
        atomicAdd(&g_counts[d], 1);
    }
}
__global__ void scan_k() {
    __shared__ int sums[1024];
    int tid = threadIdx.x;
    const int chunk = (N_NODES + 1023) / 1024;
    int start = tid * chunk;
    int end = min(start + chunk, N_NODES);
    int s = 0;
    for (int i = start; i < end; i++) s += g_counts[i];
    sums[tid] = s;
    __syncthreads();
    for (int d = 1; d < 1024; d <<= 1) {
        int v = (tid >= d) ? sums[tid - d] : 0;
        __syncthreads();
        sums[tid] += v;
        __syncthreads();
    }
    int off = sums[tid] - s;
    for (int i = start; i < end; i++) {
        g_rowptr[i] = off;
        g_cursor[i] = off;
        off += g_counts[i];
    }
    if (end == N_NODES) g_rowptr[N_NODES] = off;
}
__global__ void scatter_k(const int* __restrict__ ei) {
    int e = blockIdx.x * blockDim.x + threadIdx.x;
    if (e < E_TOT) {
        int s, d;
        if (e < N_EDGES) { s = ei[e]; d = ei[N_EDGES + e]; }
        else             { s = d = e - N_EDGES; }
        int pos = atomicAdd(&g_cursor[d], 1);
        g_csr_src[pos] = s;
    }
}

// ---------------- prep kernels ---------------------------------------------------
__global__ void transpose_rnd_k(const float* __restrict__ W, float* __restrict__ Bt, int K) {
    int idx = blockIdx.x * blockDim.x + threadIdx.x;
    if (idx >= 256 * K) return;
    int n = idx / K, k = idx - n * K;
    Bt[idx] = tf32r(W[k * 256 + n]);
}
__global__ void round_k(const float* __restrict__ in, float* __restrict__ o, int n) {
    int i = blockIdx.x * blockDim.x + threadIdx.x;
    if (i < n) o[i] = tf32r(in[i]);
}

// ---------------- 3-stage cp.async tf32 GEMM, tile 128x256, fused alpha ----------
// C is stored as fp16 (half2 per 2 cols); alpha dots computed from fp32 regs.
#define SMS 36
#define TILE_AF (128 * SMS)
#define TILE_BF (256 * SMS)
#define STAGES 3
#define GEMM_SMEM (STAGES * (TILE_AF + TILE_BF) * 4)   // 165888 B

__global__ __launch_bounds__(256, 1) void gemm_mma(
    const float* __restrict__ A, const float* __restrict__ Bt,
    __half* __restrict__ C,
    const float* __restrict__ avs, const float* __restrict__ avd,
    int M, int K)
{
    extern __shared__ float sm[];
    float* Abuf = sm;                          // [STAGES][TILE_AF]
    float* Bbuf = sm + STAGES * TILE_AF;       // [STAGES][TILE_BF]
    uint32_t sA0 = (uint32_t)__cvta_generic_to_shared(Abuf);
    uint32_t sB0 = (uint32_t)__cvta_generic_to_shared(Bbuf);

    int t = threadIdx.x;
    int lane = t & 31, wid = t >> 5;
    int wm = wid & 1, wn = wid >> 1;     // 2 x 4 warp grid
    int g = lane >> 2, tg = lane & 3;
    int row0 = blockIdx.x * 128;

    const int nch = K >> 5;

    auto issue = [&](int kc, int stg) {
        int k0 = kc << 5;
        uint32_t sa = sA0 + stg * (TILE_AF * 4);
        uint32_t sb = sB0 + stg * (TILE_BF * 4);
#pragma unroll
        for (int i = 0; i < 4; i++) {            // A: 128 rows x 8 float4
            int idx = t + (i << 8);
            int r = idx >> 3, c16 = (idx & 7) << 2;
            int gr = row0 + r;
            const float* srcA = A + (size_t)min(gr, M - 1) * K + k0 + c16;
            cpa16(sa + (r * SMS + c16) * 4, srcA, gr < M ? 16 : 0);
        }
#pragma unroll
        for (int i = 0; i < 8; i++) {            // B: 256 rows x 8 float4
            int idx = t + (i << 8);
            int r = idx >> 3, c16 = (idx & 7) << 2;
            const float* srcB = Bt + (size_t)r * K + k0 + c16;
            cpa16(sb + (r * SMS + c16) * 4, srcB, 16);
        }
        asm volatile("cp.async.commit_group;" ::: "memory");
    };

    float c[4][8][4] = {};
    issue(0, 0);
    issue(1, 1);

    for (int kc = 0; kc < nch; kc++) {
        int stg = kc % STAGES;
        if (kc + 2 < nch) {
            issue(kc + 2, (kc + 2) % STAGES);
            asm volatile("cp.async.wait_group 2;" ::: "memory");
        } else if (kc + 1 < nch) {
            asm volatile("cp.async.wait_group 1;" ::: "memory");
        } else {
            asm volatile("cp.async.wait_group 0;" ::: "memory");
        }
        __syncthreads();
        const float* Ab = Abuf + stg * TILE_AF;
        const float* Bb = Bbuf + stg * TILE_BF;
#pragma unroll
        for (int ks = 0; ks < 4; ks++) {
            int kb = ks * 8;
            uint32_t a[4][4], b[8][2];
#pragma unroll
            for (int mf = 0; mf < 4; mf++) {
                int r = wm * 64 + mf * 16 + g;
                a[mf][0] = __float_as_uint(Ab[r * SMS + kb + tg]);
                a[mf][1] = __float_as_uint(Ab[(r + 8) * SMS + kb + tg]);
                a[mf][2] = __float_as_uint(Ab[r * SMS + kb + tg + 4]);
                a[mf][3] = __float_as_uint(Ab[(r + 8) * SMS + kb + tg + 4]);
            }
#pragma unroll
            for (int nf = 0; nf < 8; nf++) {
                int n = wn * 64 + nf * 8 + g;
                b[nf][0] = __float_as_uint(Bb[n * SMS + kb + tg]);
                b[nf][1] = __float_as_uint(Bb[n * SMS + kb + tg + 4]);
            }
#pragma unroll
            for (int mf = 0; mf < 4; mf++)
#pragma unroll
                for (int nf = 0; nf < 8; nf++)
                    asm volatile(
                        "mma.sync.aligned.m16n8k8.row.col.f32.tf32.tf32.f32 "
                        "{%0,%1,%2,%3}, {%4,%5,%6,%7}, {%8,%9}, {%0,%1,%2,%3};"
                        : "+f"(c[mf][nf][0]), "+f"(c[mf][nf][1]),
                          "+f"(c[mf][nf][2]), "+f"(c[mf][nf][3])
                        : "r"(a[mf][0]), "r"(a[mf][1]), "r"(a[mf][2]), "r"(a[mf][3]),
                          "r"(b[nf][0]), "r"(b[nf][1]));
        }
        __syncthreads();
    }

    // epilogue: store C (fp16) + fused attention dots (warp column band = one head)
    int head = wn;
#pragma unroll
    for (int mf = 0; mf < 4; mf++) {
        int r0 = row0 + wm * 64 + mf * 16 + g;
        int r1 = r0 + 8;
        float sv0 = 0.f, sv1 = 0.f, dv0 = 0.f, dv1 = 0.f;
#pragma unroll
        for (int nf = 0; nf < 8; nf++) {
            int col = wn * 64 + nf * 8 + tg * 2;
            float x0 = c[mf][nf][0], x1 = c[mf][nf][1];
            float x2 = c[mf][nf][2], x3 = c[mf][nf][3];
            if (r0 < M)
                *(__half2*)(C + (size_t)r0 * NCOLS + col) = __floats2half2_rn(x0, x1);
            if (r1 < M)
                *(__half2*)(C + (size_t)r1 * NCOLS + col) = __floats2half2_rn(x2, x3);
            float w0 = __ldg(avs + col), w1 = __ldg(avs + col + 1);
            float u0 = __ldg(avd + col), u1 = __ldg(avd + col + 1);
            sv0 += x0 * w0 + x1 * w1;
            sv1 += x2 * w0 + x3 * w1;
            dv0 += x0 * u0 + x1 * u1;
            dv1 += x2 * u0 + x3 * u1;
        }
        sv0 += __shfl_xor_sync(0xffffffffu, sv0, 1);
        sv0 += __shfl_xor_sync(0xffffffffu, sv0, 2);
        sv1 += __shfl_xor_sync(0xffffffffu, sv1, 1);
        sv1 += __shfl_xor_sync(0xffffffffu, sv1, 2);
        dv0 += __shfl_xor_sync(0xffffffffu, dv0, 1);
        dv0 += __shfl_xor_sync(0xffffffffu, dv0, 2);
        dv1 += __shfl_xor_sync(0xffffffffu, dv1, 1);
        dv1 += __shfl_xor_sync(0xffffffffu, dv1, 2);
        if (tg == 0) {
            if (r0 < M) { g_asrc[r0 * 4 + head] = sv0; g_adst[r0 * 4 + head] = dv0; }
            if (r1 < M) { g_asrc[r1 * 4 + head] = sv1; g_adst[r1 * 4 + head] = dv1; }
        }
    }
}

// ---------------- aggregation: one warp per dst, fp16 gather ---------------------
// lane owns channels [lane*8, lane*8+8)  (head = lane>>3); one uint4 = 8 halves.
__global__ __launch_bounds__(256) void aggr_k(
    const __half* __restrict__ h, const float* __restrict__ bias,
    float* __restrict__ out, int do_round)
{
    __shared__ float sw[8][128];   // per-warp chunk weights [edge][head]
    int d    = (blockIdx.x * blockDim.x + threadIdx.x) >> 5;
    int lane = threadIdx.x & 31;
    int wblk = threadIdx.x >> 5;
    if (d >= N_NODES) return;
    int hol = lane >> 3;
    float* swp = sw[wblk];

    int beg = g_rowptr[d];
    int end = g_rowptr[d + 1];
    float4 adst4 = *(const float4*)(g_adst + d * 4);

    float4 m4 = make_float4(-1e30f, -1e30f, -1e30f, -1e30f);
    float4 ssum4 = make_float4(0.f, 0.f, 0.f, 0.f);
    float4 acc0 = make_float4(0.f, 0.f, 0.f, 0.f);
    float4 acc1 = make_float4(0.f, 0.f, 0.f, 0.f);

    for (int base = beg; base < end; base += 32) {
        int i = base + lane;
        bool v = i < end;
        int s_l = v ? g_csr_src[i] : 0;
        float4 e4 = make_float4(-1e30f, -1e30f, -1e30f, -1e30f);
        if (v) {
            float4 as4 = *(const float4*)(g_asrc + s_l * 4);
            float ex = as4.x + adst4.x, ey = as4.y + adst4.y;
            float ez = as4.z + adst4.z, ew = as4.w + adst4.w;
            e4.x = ex > 0.f ? ex : SLOPE * ex;
            e4.y = ey > 0.f ? ey : SLOPE * ey;
            e4.z = ez > 0.f ? ez : SLOPE * ez;
            e4.w = ew > 0.f ? ew : SLOPE * ew;
        }
        float4 cm = e4;
#pragma unroll
        for (int o = 16; o; o >>= 1) {
            cm.x = fmaxf(cm.x, __shfl_xor_sync(0xffffffffu, cm.x, o));
            cm.y = fmaxf(cm.y, __shfl_xor_sync(0xffffffffu, cm.y, o));
            cm.z = fmaxf(cm.z, __shfl_xor_sync(0xffffffffu, cm.z, o));
            cm.w = fmaxf(cm.w, __shfl_xor_sync(0xffffffffu, cm.w, o));
        }
        float4 mn = make_float4(fmaxf(m4.x, cm.x), fmaxf(m4.y, cm.y),
                                fmaxf(m4.z, cm.z), fmaxf(m4.w, cm.w));
        float4 sc = make_float4(__expf(m4.x - mn.x), __expf(m4.y - mn.y),
                                __expf(m4.z - mn.z), __expf(m4.w - mn.w));
        m4 = mn;
        ssum4.x *= sc.x; ssum4.y *= sc.y; ssum4.z *= sc.z; ssum4.w *= sc.w;
        float scl = comp4(sc, hol);
        acc0.x *= scl; acc0.y *= scl; acc0.z *= scl; acc0.w *= scl;
        acc1.x *= scl; acc1.y *= scl; acc1.z *= scl; acc1.w *= scl;

        float4 w4 = make_float4(0.f, 0.f, 0.f, 0.f);
        if (v) {
            w4.x = __expf(e4.x - m4.x);
            w4.y = __expf(e4.y - m4.y);
            w4.z = __expf(e4.z - m4.z);
            w4.w = __expf(e4.w - m4.w);
        }
        float4 ws = w4;
#pragma unroll
        for (int o = 16; o; o >>= 1) {
            ws.x += __shfl_xor_sync(0xffffffffu, ws.x, o);
            ws.y += __shfl_xor_sync(0xffffffffu, ws.y, o);
            ws.z += __shfl_xor_sync(0xffffffffu, ws.z, o);
            ws.w += __shfl_xor_sync(0xffffffffu, ws.w, o);
        }
        ssum4.x += ws.x; ssum4.y += ws.y; ssum4.z += ws.z; ssum4.w += ws.w;

        *(float4*)(swp + lane * 4) = w4;
        __syncwarp();

        int n = min(32, end - base);
        int j = 0;
        for (; j + 4 <= n; j += 4) {
            int s0 = __shfl_sync(0xffffffffu, s_l, j);
            int s1 = __shfl_sync(0xffffffffu, s_l, j + 1);
            int s2 = __shfl_sync(0xffffffffu, s_l, j + 2);
            int s3 = __shfl_sync(0xffffffffu, s_l, j + 3);
            float w0 = swp[j * 4 + hol];
            float w1 = swp[j * 4 + 4 + hol];
            float w2 = swp[j * 4 + 8 + hol];
            float w3 = swp[j * 4 + 12 + hol];
            uint4 v0 = *(const uint4*)(h + (size_t)s0 * NCOLS + lane * 8);
            uint4 v1 = *(const uint4*)(h + (size_t)s1 * NCOLS + lane * 8);
            uint4 v2 = *(const uint4*)(h + (size_t)s2 * NCOLS + lane * 8);
            uint4 v3 = *(const uint4*)(h + (size_t)s3 * NCOLS + lane * 8);
            const __half2* p0 = (const __half2*)&v0;
            const __half2* p1 = (const __half2*)&v1;
            const __half2* p2 = (const __half2*)&v2;
            const __half2* p3 = (const __half2*)&v3;
#pragma unroll
            for (int q = 0; q < 2; q++) {
                float2 f0 = __half22float2(p0[q]), f0b = __half22float2(p0[q + 2]);
                float2 f1 = __half22float2(p1[q]), f1b = __half22float2(p1[q + 2]);
                float2 f2 = __half22float2(p2[q]), f2b = __half22float2(p2[q + 2]);
                float2 f3 = __half22float2(p3[q]), f3b = __half22float2(p3[q + 2]);
                float* a0 = (q == 0) ? &acc0.x : &acc0.z;
                float* a1 = (q == 0) ? &acc1.x : &acc1.z;
                a0[0] += w0 * f0.x + w1 * f1.x + w2 * f2.x + w3 * f3.x;
                a0[1] += w0 * f0.y + w1 * f1.y + w2 * f2.y + w3 * f3.y;
                a1[0] += w0 * f0b.x + w1 * f1b.x + w2 * f2b.x + w3 * f3b.x;
                a1[1] += w0 * f0b.y + w1 * f1b.y + w2 * f2b.y + w3 * f3b.y;
            }
        }
        for (; j < n; j++) {
            int s0 = __shfl_sync(0xffffffffu, s_l, j);
            float w0 = swp[j * 4 + hol];
            uint4 v0 = *(const uint4*)(h + (size_t)s0 * NCOLS + lane * 8);
            const __half2* p0 = (const __half2*)&v0;
            float2 f0 = __half22float2(p0[0]);
            float2 f1 = __half22float2(p0[1]);
            float2 f2 = __half22float2(p0[2]);
            float2 f3 = __half22float2(p0[3]);
            acc0.x += w0 * f0.x; acc0.y += w0 * f0.y;
            acc0.z += w0 * f1.x; acc0.w += w0 * f1.y;
            acc1.x += w0 * f2.x; acc1.y += w0 * f2.y;
            acc1.z += w0 * f3.x; acc1.w += w0 * f3.y;
        }
        __syncwarp();
    }

    float inv = 1.f / comp4(ssum4, hol);
    int c0 = lane * 8;
    float4 bb0 = *(const float4*)(bias + c0);
    float4 bb1 = *(const float4*)(bias + c0 + 4);
    float o_[8];
    o_[0] = acc0.x * inv + bb0.x; o_[1] = acc0.y * inv + bb0.y;
    o_[2] = acc0.z * inv + bb0.z; o_[3] = acc0.w * inv + bb0.w;
    o_[4] = acc1.x * inv + bb1.x; o_[5] = acc1.y * inv + bb1.y;
    o_[6] = acc1.z * inv + bb1.z; o_[7] = acc1.w * inv + bb1.w;
#pragma unroll
    for (int k = 0; k < 8; k++) {
        float o = o_[k];
        o = o > 0.f ? o : (__expf(o) - 1.f);
        if (do_round) o = tf32r(o);
        o_[k] = o;
    }
    *(float4*)(out + (size_t)d * NCOLS + c0)     = make_float4(o_[0], o_[1], o_[2], o_[3]);
    *(float4*)(out + (size_t)d * NCOLS + c0 + 4) = make_float4(o_[4], o_[5], o_[6], o_[7]);
}

// ---------------- driver ---------------------------------------------------------
extern "C" void kernel_launch(void* const* d_in, const int* in_sizes, int n_in,
                              void* d_out, int out_size)
{
    const float* inp = (const float*)d_in[0];
    const int*   ei  = (const int*)d_in[1];
    const float* W1  = (const float*)d_in[2];
    const float* as1 = (const float*)d_in[3];
    const float* ad1 = (const float*)d_in[4];
    const float* b1  = (const float*)d_in[5];
    const float* W2  = (const float*)d_in[6];
    const float* as2 = (const float*)d_in[7];
    const float* ad2 = (const float*)d_in[8];
    const float* b2  = (const float*)d_in[9];
    const float* W3  = (const float*)d_in[10];
    const float* as3 = (const float*)d_in[11];
    const float* ad3 = (const float*)d_in[12];
    const float* b3  = (const float*)d_in[13];
    float* out = (float*)d_out;

    __half* hbuf;
    float *xbuf, *bt1, *bt2, *bt3;
    cudaGetSymbolAddress((void**)&hbuf, g_h);
    cudaGetSymbolAddress((void**)&xbuf, g_x);
    cudaGetSymbolAddress((void**)&bt1, g_bt1);
    cudaGetSymbolAddress((void**)&bt2, g_bt2);
    cudaGetSymbolAddress((void**)&bt3, g_bt3);

    cudaFuncSetAttribute(gemm_mma, cudaFuncAttributeMaxDynamicSharedMemorySize, GEMM_SMEM);

    // fork/join resources, created once on the (un-captured) correctness call
    static cudaStream_t s2 = nullptr;
    static cudaEvent_t e_fork = nullptr, e_join = nullptr;
    if (!s2) {
        cudaStreamCreateWithFlags(&s2, cudaStreamNonBlocking);
        cudaEventCreateWithFlags(&e_fork, cudaEventDisableTiming);
        cudaEventCreateWithFlags(&e_join, cudaEventDisableTiming);
    }

    // fork: CSR build on s2 (only gates aggr_k of layer 1)
    cudaEventRecord(e_fork, 0);
    cudaStreamWaitEvent(s2, e_fork, 0);
    zero_counts_k<<<(N_NODES + 255) / 256, 256, 0, s2>>>();
    hist_k<<<(E_TOT + 255) / 256, 256, 0, s2>>>(ei);
    scan_k<<<1, 1024, 0, s2>>>();
    scatter_k<<<(E_TOT + 255) / 256, 256, 0, s2>>>(ei);
    cudaEventRecord(e_join, s2);

    // main stream: weight prep + layer-1 GEMM run concurrently with CSR
    transpose_rnd_k<<<(256 * 128 + 255) / 256, 256>>>(W1, bt1, 128);
    transpose_rnd_k<<<(256 * 256 + 255) / 256, 256>>>(W2, bt2, 256);
    transpose_rnd_k<<<(256 * 256 + 255) / 256, 256>>>(W3, bt3, 256);
    round_k<<<(N_NODES * 128 + 255) / 256, 256>>>(inp, xbuf, N_NODES * 128);

    int ggrid = (N_NODES + 127) / 128;
    int agrid = (N_NODES * 32 + 255) / 256;

    gemm_mma<<<ggrid, 256, GEMM_SMEM>>>(xbuf, bt1, hbuf, as1, ad1, N_NODES, 128);
    cudaStreamWaitEvent(0, e_join, 0);   // join: CSR ready before first aggregation
    aggr_k<<<agrid, 256>>>(hbuf, b1, xbuf, 1);

    gemm_mma<<<ggrid, 256, GEMM_SMEM>>>(xbuf, bt2, hbuf, as2, ad2, N_NODES, 256);
    aggr_k<<<agrid, 256>>>(hbuf, b2, xbuf, 1);

    gemm_mma<<<ggrid, 256, GEMM_SMEM>>>(xbuf, bt3, hbuf, as3, ad3, N_NODES, 256);
    aggr_k<<<agrid, 256>>>(hbuf, b3, out, 0);
}

// round 8
// speedup vs baseline: 3.0463x; 1.1232x over previous
#include <cuda_runtime.h>
#include <cuda_fp16.h>
#include <cstdint>

#define N_NODES 50000
#define N_EDGES 800000
#define E_TOT   (N_EDGES + N_NODES)
#define NCOLS   256
#define SLOPE   0.2f

// ---------------- scratch (device globals) -----------------------------------
__device__ __half g_h[N_NODES * NCOLS];      // GEMM output (gather source), fp16
__device__ __half g_xh[N_NODES * NCOLS];     // layer activations, fp16
__device__ __half g_bt1[256 * 128];          // W^T fp16, [n][k]
__device__ __half g_bt2[256 * 256];
__device__ __half g_bt3[256 * 256];
__device__ float  g_asrc[N_NODES * 4];
__device__ float  g_adst[N_NODES * 4];
__device__ int    g_counts[N_NODES];
__device__ int    g_rowptr[N_NODES + 1];
__device__ int    g_cursor[N_NODES];
__device__ int    g_csr_src[E_TOT];

__device__ __forceinline__ void cpa16(uint32_t sdst, const void* gsrc, int srcsize) {
    asm volatile("cp.async.cg.shared.global [%0], [%1], 16, %2;"
                 :: "r"(sdst), "l"(gsrc), "r"(srcsize));
}
__device__ __forceinline__ float comp4(float4 v, int i) {
    float r = v.x;
    r = (i == 1) ? v.y : r;
    r = (i == 2) ? v.z : r;
    r = (i == 3) ? v.w : r;
    return r;
}

// ---------------- CSR build ----------------------------------------------------
__global__ void zero_counts_k() {
    int i = blockIdx.x * blockDim.x + threadIdx.x;
    if (i < N_NODES) g_counts[i] = 0;
}
__global__ void hist_k(const int* __restrict__ ei) {
    int e = blockIdx.x * blockDim.x + threadIdx.x;
    if (e < E_TOT) {
        int d = (e < N_EDGES) ? ei[N_EDGES + e] : (e - N_EDGES);
        atomicAdd(&g_counts[d], 1);
    }
}
__global__ void scan_k() {
    __shared__ int sums[1024];
    int tid = threadIdx.x;
    const int chunk = (N_NODES + 1023) / 1024;
    int start = tid * chunk;
    int end = min(start + chunk, N_NODES);
    int s = 0;
    for (int i = start; i < end; i++) s += g_counts[i];
    sums[tid] = s;
    __syncthreads();
    for (int d = 1; d < 1024; d <<= 1) {
        int v = (tid >= d) ? sums[tid - d] : 0;
        __syncthreads();
        sums[tid] += v;
        __syncthreads();
    }
    int off = sums[tid] - s;
    for (int i = start; i < end; i++) {
        g_rowptr[i] = off;
        g_cursor[i] = off;
        off += g_counts[i];
    }
    if (end == N_NODES) g_rowptr[N_NODES] = off;
}
__global__ void scatter_k(const int* __restrict__ ei) {
    int e = blockIdx.x * blockDim.x + threadIdx.x;
    if (e < E_TOT) {
        int s, d;
        if (e < N_EDGES) { s = ei[e]; d = ei[N_EDGES + e]; }
        else             { s = d = e - N_EDGES; }
        int pos = atomicAdd(&g_cursor[d], 1);
        g_csr_src[pos] = s;
    }
}

// ---------------- prep kernels ---------------------------------------------------
__global__ void transpose_h_k(const float* __restrict__ W, __half* __restrict__ Bt, int K) {
    int idx = blockIdx.x * blockDim.x + threadIdx.x;
    if (idx >= 256 * K) return;
    int n = idx / K, k = idx - n * K;
    Bt[idx] = __float2half_rn(W[k * 256 + n]);
}
__global__ void tohalf_k(const float* __restrict__ in, __half* __restrict__ o, int n) {
    int i = blockIdx.x * blockDim.x + threadIdx.x;
    if (i < n) o[i] = __float2half_rn(in[i]);
}

// ---------------- 3-stage cp.async fp16 GEMM, tile 128x256, fused alpha ----------
// mma.m16n8k16.f16 with fp32 accumulate. Half stride 40 -> bank (20r+tg)%32, CF.
#define SMS_H 40
#define TILE_AH (128 * SMS_H)    // halves
#define TILE_BH (256 * SMS_H)
#define STAGES 3
#define GEMM_SMEM (STAGES * (TILE_AH + TILE_BH) * 2)   // 92160 B

__global__ __launch_bounds__(256, 1) void gemm_mma(
    const __half* __restrict__ A, const __half* __restrict__ Bt,
    __half* __restrict__ C,
    const float* __restrict__ avs, const float* __restrict__ avd,
    int M, int K)
{
    extern __shared__ __half smh[];
    __half* Abuf = smh;                          // [STAGES][TILE_AH]
    __half* Bbuf = smh + STAGES * TILE_AH;       // [STAGES][TILE_BH]
    uint32_t sA0 = (uint32_t)__cvta_generic_to_shared(Abuf);
    uint32_t sB0 = (uint32_t)__cvta_generic_to_shared(Bbuf);

    int t = threadIdx.x;
    int lane = t & 31, wid = t >> 5;
    int wm = wid & 1, wn = wid >> 1;     // 2 x 4 warp grid, warp tile 64x64
    int g = lane >> 2, tg = lane & 3;
    int row0 = blockIdx.x * 128;

    const int nch = K >> 5;

    auto issue = [&](int kc, int stg) {
        int k0 = kc << 5;
        uint32_t sa = sA0 + stg * (TILE_AH * 2);
        uint32_t sb = sB0 + stg * (TILE_BH * 2);
#pragma unroll
        for (int i = 0; i < 2; i++) {            // A: 128 rows x 4 x 16B
            int idx = t + (i << 8);
            int r = idx >> 2, c8 = (idx & 3) << 3;
            int gr = row0 + r;
            const __half* srcA = A + (size_t)min(gr, M - 1) * K + k0 + c8;
            cpa16(sa + (r * SMS_H + c8) * 2, srcA, gr < M ? 16 : 0);
        }
#pragma unroll
        for (int i = 0; i < 4; i++) {            // B: 256 rows x 4 x 16B
            int idx = t + (i << 8);
            int r = idx >> 2, c8 = (idx & 3) << 3;
            const __half* srcB = Bt + (size_t)r * K + k0 + c8;
            cpa16(sb + (r * SMS_H + c8) * 2, srcB, 16);
        }
        asm volatile("cp.async.commit_group;" ::: "memory");
    };

    float c[4][8][4] = {};
    issue(0, 0);
    issue(1, 1);

    for (int kc = 0; kc < nch; kc++) {
        int stg = kc % STAGES;
        if (kc + 2 < nch) {
            issue(kc + 2, (kc + 2) % STAGES);
            asm volatile("cp.async.wait_group 2;" ::: "memory");
        } else if (kc + 1 < nch) {
            asm volatile("cp.async.wait_group 1;" ::: "memory");
        } else {
            asm volatile("cp.async.wait_group 0;" ::: "memory");
        }
        __syncthreads();
        const __half* Ab = Abuf + stg * TILE_AH;
        const __half* Bb = Bbuf + stg * TILE_BH;
#pragma unroll
        for (int ks = 0; ks < 2; ks++) {
            int kb = ks * 16;
            uint32_t a[4][4], b[8][2];
#pragma unroll
            for (int mf = 0; mf < 4; mf++) {
                int r = wm * 64 + mf * 16 + g;
                a[mf][0] = *(const uint32_t*)&Ab[r * SMS_H + kb + 2 * tg];
                a[mf][1] = *(const uint32_t*)&Ab[(r + 8) * SMS_H + kb + 2 * tg];
                a[mf][2] = *(const uint32_t*)&Ab[r * SMS_H + kb + 2 * tg + 8];
                a[mf][3] = *(const uint32_t*)&Ab[(r + 8) * SMS_H + kb + 2 * tg + 8];
            }
#pragma unroll
            for (int nf = 0; nf < 8; nf++) {
                int n = wn * 64 + nf * 8 + g;
                b[nf][0] = *(const uint32_t*)&Bb[n * SMS_H + kb + 2 * tg];
                b[nf][1] = *(const uint32_t*)&Bb[n * SMS_H + kb + 2 * tg + 8];
            }
#pragma unroll
            for (int mf = 0; mf < 4; mf++)
#pragma unroll
                for (int nf = 0; nf < 8; nf++)
                    asm volatile(
                        "mma.sync.aligned.m16n8k16.row.col.f32.f16.f16.f32 "
                        "{%0,%1,%2,%3}, {%4,%5,%6,%7}, {%8,%9}, {%0,%1,%2,%3};"
                        : "+f"(c[mf][nf][0]), "+f"(c[mf][nf][1]),
                          "+f"(c[mf][nf][2]), "+f"(c[mf][nf][3])
                        : "r"(a[mf][0]), "r"(a[mf][1]), "r"(a[mf][2]), "r"(a[mf][3]),
                          "r"(b[nf][0]), "r"(b[nf][1]));
        }
        __syncthreads();
    }

    // epilogue: store C (fp16) + fused attention dots (warp column band = one head)
    int head = wn;
#pragma unroll
    for (int mf = 0; mf < 4; mf++) {
        int r0 = row0 + wm * 64 + mf * 16 + g;
        int r1 = r0 + 8;
        float sv0 = 0.f, sv1 = 0.f, dv0 = 0.f, dv1 = 0.f;
#pragma unroll
        for (int nf = 0; nf < 8; nf++) {
            int col = wn * 64 + nf * 8 + tg * 2;
            float x0 = c[mf][nf][0], x1 = c[mf][nf][1];
            float x2 = c[mf][nf][2], x3 = c[mf][nf][3];
            if (r0 < M)
                *(__half2*)(C + (size_t)r0 * NCOLS + col) = __floats2half2_rn(x0, x1);
            if (r1 < M)
                *(__half2*)(C + (size_t)r1 * NCOLS + col) = __floats2half2_rn(x2, x3);
            float w0 = __ldg(avs + col), w1 = __ldg(avs + col + 1);
            float u0 = __ldg(avd + col), u1 = __ldg(avd + col + 1);
            sv0 += x0 * w0 + x1 * w1;
            sv1 += x2 * w0 + x3 * w1;
            dv0 += x0 * u0 + x1 * u1;
            dv1 += x2 * u0 + x3 * u1;
        }
        sv0 += __shfl_xor_sync(0xffffffffu, sv0, 1);
        sv0 += __shfl_xor_sync(0xffffffffu, sv0, 2);
        sv1 += __shfl_xor_sync(0xffffffffu, sv1, 1);
        sv1 += __shfl_xor_sync(0xffffffffu, sv1, 2);
        dv0 += __shfl_xor_sync(0xffffffffu, dv0, 1);
        dv0 += __shfl_xor_sync(0xffffffffu, dv0, 2);
        dv1 += __shfl_xor_sync(0xffffffffu, dv1, 1);
        dv1 += __shfl_xor_sync(0xffffffffu, dv1, 2);
        if (tg == 0) {
            if (r0 < M) { g_asrc[r0 * 4 + head] = sv0; g_adst[r0 * 4 + head] = dv0; }
            if (r1 < M) { g_asrc[r1 * 4 + head] = sv1; g_adst[r1 * 4 + head] = dv1; }
        }
    }
}

// ---------------- aggregation: one warp per dst, fp16 gather ---------------------
// lane owns channels [lane*8, lane*8+8)  (head = lane>>3); shared max across heads.
__global__ __launch_bounds__(256) void aggr_k(
    const __half* __restrict__ h, const float* __restrict__ bias,
    __half* __restrict__ out_h, float* __restrict__ out_f)
{
    __shared__ float sw[8][128];   // per-warp chunk weights [edge][head]
    int d    = (blockIdx.x * blockDim.x + threadIdx.x) >> 5;
    int lane = threadIdx.x & 31;
    int wblk = threadIdx.x >> 5;
    if (d >= N_NODES) return;
    int hol = lane >> 3;
    float* swp = sw[wblk];

    int beg = g_rowptr[d];
    int end = g_rowptr[d + 1];
    float4 adst4 = *(const float4*)(g_adst + d * 4);

    float m = -1e30f;
    float4 ssum4 = make_float4(0.f, 0.f, 0.f, 0.f);
    float4 acc0 = make_float4(0.f, 0.f, 0.f, 0.f);
    float4 acc1 = make_float4(0.f, 0.f, 0.f, 0.f);

    for (int base = beg; base < end; base += 32) {
        int i = base + lane;
        bool v = i < end;
        int s_l = v ? g_csr_src[i] : 0;
        float4 e4 = make_float4(-1e30f, -1e30f, -1e30f, -1e30f);
        if (v) {
            float4 as4 = *(const float4*)(g_asrc + s_l * 4);
            float ex = as4.x + adst4.x, ey = as4.y + adst4.y;
            float ez = as4.z + adst4.z, ew = as4.w + adst4.w;
            e4.x = ex > 0.f ? ex : SLOPE * ex;
            e4.y = ey > 0.f ? ey : SLOPE * ey;
            e4.z = ez > 0.f ? ez : SLOPE * ez;
            e4.w = ew > 0.f ? ew : SLOPE * ew;
        }
        // single chunk max across heads (softmax is shift-invariant per head)
        float em = fmaxf(fmaxf(e4.x, e4.y), fmaxf(e4.z, e4.w));
#pragma unroll
        for (int o = 16; o; o >>= 1)
            em = fmaxf(em, __shfl_xor_sync(0xffffffffu, em, o));
        float mn = fmaxf(m, em);
        float sc = __expf(m - mn);
        m = mn;
        ssum4.x *= sc; ssum4.y *= sc; ssum4.z *= sc; ssum4.w *= sc;
        acc0.x *= sc; acc0.y *= sc; acc0.z *= sc; acc0.w *= sc;
        acc1.x *= sc; acc1.y *= sc; acc1.z *= sc; acc1.w *= sc;

        float4 w4 = make_float4(0.f, 0.f, 0.f, 0.f);
        if (v) {
            w4.x = __expf(e4.x - m);
            w4.y = __expf(e4.y - m);
            w4.z = __expf(e4.z - m);
            w4.w = __expf(e4.w - m);
        }
        float4 ws = w4;
#pragma unroll
        for (int o = 16; o; o >>= 1) {
            ws.x += __shfl_xor_sync(0xffffffffu, ws.x, o);
            ws.y += __shfl_xor_sync(0xffffffffu, ws.y, o);
            ws.z += __shfl_xor_sync(0xffffffffu, ws.z, o);
            ws.w += __shfl_xor_sync(0xffffffffu, ws.w, o);
        }
        ssum4.x += ws.x; ssum4.y += ws.y; ssum4.z += ws.z; ssum4.w += ws.w;

        *(float4*)(swp + lane * 4) = w4;
        __syncwarp();

        int n = min(32, end - base);
        int j = 0;
        for (; j + 4 <= n; j += 4) {
            int s0 = __shfl_sync(0xffffffffu, s_l, j);
            int s1 = __shfl_sync(0xffffffffu, s_l, j + 1);
            int s2 = __shfl_sync(0xffffffffu, s_l, j + 2);
            int s3 = __shfl_sync(0xffffffffu, s_l, j + 3);
            float w0 = swp[j * 4 + hol];
            float w1 = swp[j * 4 + 4 + hol];
            float w2 = swp[j * 4 + 8 + hol];
            float w3 = swp[j * 4 + 12 + hol];
            uint4 v0 = *(const uint4*)(h + (size_t)s0 * NCOLS + lane * 8);
            uint4 v1 = *(const uint4*)(h + (size_t)s1 * NCOLS + lane * 8);
            uint4 v2 = *(const uint4*)(h + (size_t)s2 * NCOLS + lane * 8);
            uint4 v3 = *(const uint4*)(h + (size_t)s3 * NCOLS + lane * 8);
            const __half2* p0 = (const __half2*)&v0;
            const __half2* p1 = (const __half2*)&v1;
            const __half2* p2 = (const __half2*)&v2;
            const __half2* p3 = (const __half2*)&v3;
#pragma unroll
            for (int q = 0; q < 2; q++) {
                float2 f0 = __half22float2(p0[q]), f0b = __half22float2(p0[q + 2]);
                float2 f1 = __half22float2(p1[q]), f1b = __half22float2(p1[q + 2]);
                float2 f2 = __half22float2(p2[q]), f2b = __half22float2(p2[q + 2]);
                float2 f3 = __half22float2(p3[q]), f3b = __half22float2(p3[q + 2]);
                float* a0 = (q == 0) ? &acc0.x : &acc0.z;
                float* a1 = (q == 0) ? &acc1.x : &acc1.z;
                a0[0] += w0 * f0.x + w1 * f1.x + w2 * f2.x + w3 * f3.x;
                a0[1] += w0 * f0.y + w1 * f1.y + w2 * f2.y + w3 * f3.y;
                a1[0] += w0 * f0b.x + w1 * f1b.x + w2 * f2b.x + w3 * f3b.x;
                a1[1] += w0 * f0b.y + w1 * f1b.y + w2 * f2b.y + w3 * f3b.y;
            }
        }
        for (; j < n; j++) {
            int s0 = __shfl_sync(0xffffffffu, s_l, j);
            float w0 = swp[j * 4 + hol];
            uint4 v0 = *(const uint4*)(h + (size_t)s0 * NCOLS + lane * 8);
            const __half2* p0 = (const __half2*)&v0;
            float2 f0 = __half22float2(p0[0]);
            float2 f1 = __half22float2(p0[1]);
            float2 f2 = __half22float2(p0[2]);
            float2 f3 = __half22float2(p0[3]);
            acc0.x += w0 * f0.x; acc0.y += w0 * f0.y;
            acc0.z += w0 * f1.x; acc0.w += w0 * f1.y;
            acc1.x += w0 * f2.x; acc1.y += w0 * f2.y;
            acc1.z += w0 * f3.x; acc1.w += w0 * f3.y;
        }
        __syncwarp();
    }

    float inv = 1.f / comp4(ssum4, hol);
    int c0 = lane * 8;
    float4 bb0 = *(const float4*)(bias + c0);
    float4 bb1 = *(const float4*)(bias + c0 + 4);
    float o_[8];
    o_[0] = acc0.x * inv + bb0.x; o_[1] = acc0.y * inv + bb0.y;
    o_[2] = acc0.z * inv + bb0.z; o_[3] = acc0.w * inv + bb0.w;
    o_[4] = acc1.x * inv + bb1.x; o_[5] = acc1.y * inv + bb1.y;
    o_[6] = acc1.z * inv + bb1.z; o_[7] = acc1.w * inv + bb1.w;
#pragma unroll
    for (int k = 0; k < 8; k++) {
        float o = o_[k];
        o_[k] = o > 0.f ? o : (__expf(o) - 1.f);
    }
    if (out_h) {
        __half2 hh[4];
        hh[0] = __floats2half2_rn(o_[0], o_[1]);
        hh[1] = __floats2half2_rn(o_[2], o_[3]);
        hh[2] = __floats2half2_rn(o_[4], o_[5]);
        hh[3] = __floats2half2_rn(o_[6], o_[7]);
        *(uint4*)(out_h + (size_t)d * NCOLS + c0) = *(uint4*)hh;
    } else {
        *(float4*)(out_f + (size_t)d * NCOLS + c0)     = make_float4(o_[0], o_[1], o_[2], o_[3]);
        *(float4*)(out_f + (size_t)d * NCOLS + c0 + 4) = make_float4(o_[4], o_[5], o_[6], o_[7]);
    }
}

// ---------------- driver ---------------------------------------------------------
extern "C" void kernel_launch(void* const* d_in, const int* in_sizes, int n_in,
                              void* d_out, int out_size)
{
    const float* inp = (const float*)d_in[0];
    const int*   ei  = (const int*)d_in[1];
    const float* W1  = (const float*)d_in[2];
    const float* as1 = (const float*)d_in[3];
    const float* ad1 = (const float*)d_in[4];
    const float* b1  = (const float*)d_in[5];
    const float* W2  = (const float*)d_in[6];
    const float* as2 = (const float*)d_in[7];
    const float* ad2 = (const float*)d_in[8];
    const float* b2  = (const float*)d_in[9];
    const float* W3  = (const float*)d_in[10];
    const float* as3 = (const float*)d_in[11];
    const float* ad3 = (const float*)d_in[12];
    const float* b3  = (const float*)d_in[13];
    float* out = (float*)d_out;

    __half *hbuf, *xh, *bt1, *bt2, *bt3;
    cudaGetSymbolAddress((void**)&hbuf, g_h);
    cudaGetSymbolAddress((void**)&xh, g_xh);
    cudaGetSymbolAddress((void**)&bt1, g_bt1);
    cudaGetSymbolAddress((void**)&bt2, g_bt2);
    cudaGetSymbolAddress((void**)&bt3, g_bt3);

    cudaFuncSetAttribute(gemm_mma, cudaFuncAttributeMaxDynamicSharedMemorySize, GEMM_SMEM);

    // fork/join resources, created once on the (un-captured) correctness call
    static cudaStream_t s2 = nullptr;
    static cudaEvent_t e_fork = nullptr, e_join = nullptr;
    if (!s2) {
        cudaStreamCreateWithFlags(&s2, cudaStreamNonBlocking);
        cudaEventCreateWithFlags(&e_fork, cudaEventDisableTiming);
        cudaEventCreateWithFlags(&e_join, cudaEventDisableTiming);
    }

    // fork: CSR build on s2 (only gates aggr_k of layer 1)
    cudaEventRecord(e_fork, 0);
    cudaStreamWaitEvent(s2, e_fork, 0);
    zero_counts_k<<<(N_NODES + 255) / 256, 256, 0, s2>>>();
    hist_k<<<(E_TOT + 255) / 256, 256, 0, s2>>>(ei);
    scan_k<<<1, 1024, 0, s2>>>();
    scatter_k<<<(E_TOT + 255) / 256, 256, 0, s2>>>(ei);
    cudaEventRecord(e_join, s2);

    // main stream: weight prep + layer-1 GEMM run concurrently with CSR
    transpose_h_k<<<(256 * 128 + 255) / 256, 256>>>(W1, bt1, 128);
    transpose_h_k<<<(256 * 256 + 255) / 256, 256>>>(W2, bt2, 256);
    transpose_h_k<<<(256 * 256 + 255) / 256, 256>>>(W3, bt3, 256);
    tohalf_k<<<(N_NODES * 128 + 255) / 256, 256>>>(inp, xh, N_NODES * 128);

    int ggrid = (N_NODES + 127) / 128;
    int agrid = (N_NODES * 32 + 255) / 256;

    gemm_mma<<<ggrid, 256, GEMM_SMEM>>>(xh, bt1, hbuf, as1, ad1, N_NODES, 128);
    cudaStreamWaitEvent(0, e_join, 0);   // join: CSR ready before first aggregation
    aggr_k<<<agrid, 256>>>(hbuf, b1, xh, nullptr);

    gemm_mma<<<ggrid, 256, GEMM_SMEM>>>(xh, bt2, hbuf, as2, ad2, N_NODES, 256);
    aggr_k<<<agrid, 256>>>(hbuf, b2, xh, nullptr);

    gemm_mma<<<ggrid, 256, GEMM_SMEM>>>(xh, bt3, hbuf, as3, ad3, N_NODES, 256);
    aggr_k<<<agrid, 256>>>(hbuf, b3, nullptr, out);
}